// round 1
// baseline (speedup 1.0000x reference)
#include <cuda_runtime.h>
#include <math.h>

#define BATCH  2
#define SEQ    2048
#define DMODEL 2048
#define NHEADS 16
#define DKK    128

// Scratch (allocation-free rule: device globals)
__device__ float g_q[BATCH * SEQ * DMODEL];     // Q projection [B,S,DMODEL]
__device__ float g_attn[BATCH * SEQ * DMODEL];  // attention out [B,S,DMODEL]

// ---------------------------------------------------------------------------
// Tiled SGEMM + bias: C[M,N] = A[M,K] @ W[K,N] + bias[N]
// BM=BN=128, BK=16, 256 threads, 8x8 per thread (split 4+4 to avoid LDS conflicts)
// ---------------------------------------------------------------------------
__global__ __launch_bounds__(256) void sgemm_bias_kernel(
    const float* __restrict__ A, const float* __restrict__ W,
    const float* __restrict__ bias, float* __restrict__ C,
    int M, int N, int K)
{
    __shared__ float As[16][132];
    __shared__ float Bs[16][132];

    const int tid = threadIdx.x;
    const int tx = tid & 15;
    const int ty = tid >> 4;
    const int rowBase = blockIdx.y * 128;
    const int colBase = blockIdx.x * 128;

    float acc[8][8];
#pragma unroll
    for (int i = 0; i < 8; i++)
#pragma unroll
        for (int j = 0; j < 8; j++) acc[i][j] = 0.f;

    for (int k0 = 0; k0 < K; k0 += 16) {
        // A tile: 128 rows x 16 k, stored transposed As[k][row]
#pragma unroll
        for (int it = 0; it < 2; it++) {
            int idx = tid + it * 256;
            int r  = idx >> 2;
            int c4 = (idx & 3) << 2;
            float4 v = *(const float4*)(A + (size_t)(rowBase + r) * K + k0 + c4);
            As[c4 + 0][r] = v.x; As[c4 + 1][r] = v.y;
            As[c4 + 2][r] = v.z; As[c4 + 3][r] = v.w;
        }
        // B tile: 16 k x 128 n
#pragma unroll
        for (int it = 0; it < 2; it++) {
            int idx = tid + it * 256;
            int kr = idx >> 5;
            int c4 = (idx & 31) << 2;
            *(float4*)(&Bs[kr][c4]) =
                *(const float4*)(W + (size_t)(k0 + kr) * N + colBase + c4);
        }
        __syncthreads();

#pragma unroll
        for (int kk = 0; kk < 16; kk++) {
            float a[8], b[8];
            *(float4*)&a[0] = *(float4*)&As[kk][ty * 4];
            *(float4*)&a[4] = *(float4*)&As[kk][ty * 4 + 64];
            *(float4*)&b[0] = *(float4*)&Bs[kk][tx * 4];
            *(float4*)&b[4] = *(float4*)&Bs[kk][tx * 4 + 64];
#pragma unroll
            for (int i = 0; i < 8; i++)
#pragma unroll
                for (int j = 0; j < 8; j++)
                    acc[i][j] = fmaf(a[i], b[j], acc[i][j]);
        }
        __syncthreads();
    }

#pragma unroll
    for (int i = 0; i < 8; i++) {
        int row = rowBase + ((i < 4) ? (ty * 4 + i) : (64 + ty * 4 + (i - 4)));
#pragma unroll
        for (int jg = 0; jg < 2; jg++) {
            int col = colBase + jg * 64 + tx * 4;
            float4 o;
            o.x = acc[i][jg * 4 + 0] + bias[col + 0];
            o.y = acc[i][jg * 4 + 1] + bias[col + 1];
            o.z = acc[i][jg * 4 + 2] + bias[col + 2];
            o.w = acc[i][jg * 4 + 3] + bias[col + 3];
            *(float4*)(C + (size_t)row * N + col) = o;
        }
    }
}

// ---------------------------------------------------------------------------
// Flash attention (MQA): one CTA = (b, h, 64 query rows). Online softmax over
// S=2048 keys in 64-row tiles. 256 threads: 16x16 grid; scores 4x4/thread
// (cols tc + 16*jj), O accumulator 4 rows x 8 cols per thread.
// ---------------------------------------------------------------------------
#define QSTR 132
#define PSTR 68
#define FLASH_SMEM_BYTES ((3 * 64 * QSTR + 64 * PSTR) * 4)

__device__ __forceinline__ void dot4acc(float& s, float4 a, float4 b) {
    s = fmaf(a.x, b.x, s);
    s = fmaf(a.y, b.y, s);
    s = fmaf(a.z, b.z, s);
    s = fmaf(a.w, b.w, s);
}

__global__ __launch_bounds__(256) void flash_kernel(
    const float* __restrict__ Q,   // [B,S,DMODEL] (pre-bias-added)
    const float* __restrict__ Kc,  // [B,S,DK]
    const float* __restrict__ Vc,  // [B,S,DK]
    float* __restrict__ O)         // [B,S,DMODEL]
{
    extern __shared__ float sm[];
    float* Qs = sm;                  // 64 x QSTR
    float* Ks = Qs + 64 * QSTR;      // 64 x QSTR
    float* Vs = Ks + 64 * QSTR;      // 64 x QSTR
    float* Ps = Vs + 64 * QSTR;      // 64 x PSTR

    const int tid = threadIdx.x;
    const int tc = tid & 15;
    const int tr = tid >> 4;
    const int h = blockIdx.y;
    const int b = blockIdx.z;
    const int q0 = blockIdx.x * 64;
    const float scale = 0.08838834764831845f;  // 1/sqrt(128)

    // Load + pre-scale Q tile
    const float* Qg = Q + ((size_t)(b * SEQ + q0)) * DMODEL + h * DKK;
#pragma unroll
    for (int it = 0; it < 8; it++) {
        int idx = tid + it * 256;
        int r  = idx >> 5;
        int d4 = (idx & 31) << 2;
        float4 v = *(const float4*)(Qg + (size_t)r * DMODEL + d4);
        v.x *= scale; v.y *= scale; v.z *= scale; v.w *= scale;
        *(float4*)&Qs[r * QSTR + d4] = v;
    }

    float m_i[4], l_i[4], o[4][8];
#pragma unroll
    for (int i = 0; i < 4; i++) {
        m_i[i] = -1e30f;
        l_i[i] = 0.f;
#pragma unroll
        for (int j = 0; j < 8; j++) o[i][j] = 0.f;
    }

    const float* Kg = Kc + (size_t)b * SEQ * DKK;
    const float* Vg = Vc + (size_t)b * SEQ * DKK;

    for (int jt = 0; jt < SEQ / 64; jt++) {
        __syncthreads();  // prev-iteration PV done; Ks/Vs/Ps reusable
        const int k0 = jt * 64;
#pragma unroll
        for (int it = 0; it < 8; it++) {
            int idx = tid + it * 256;
            int r  = idx >> 5;
            int d4 = (idx & 31) << 2;
            *(float4*)&Ks[r * QSTR + d4] =
                *(const float4*)(Kg + (size_t)(k0 + r) * DKK + d4);
            *(float4*)&Vs[r * QSTR + d4] =
                *(const float4*)(Vg + (size_t)(k0 + r) * DKK + d4);
        }
        __syncthreads();

        // S = Qs @ Ks^T (scaled already). Thread cols: tc + 16*jj.
        float s[4][4];
#pragma unroll
        for (int i = 0; i < 4; i++)
#pragma unroll
            for (int j = 0; j < 4; j++) s[i][j] = 0.f;

#pragma unroll 8
        for (int d0 = 0; d0 < DKK; d0 += 4) {
            float4 a0 = *(float4*)&Qs[(tr * 4 + 0) * QSTR + d0];
            float4 a1 = *(float4*)&Qs[(tr * 4 + 1) * QSTR + d0];
            float4 a2 = *(float4*)&Qs[(tr * 4 + 2) * QSTR + d0];
            float4 a3 = *(float4*)&Qs[(tr * 4 + 3) * QSTR + d0];
            float4 b0 = *(float4*)&Ks[(tc + 0)  * QSTR + d0];
            float4 b1 = *(float4*)&Ks[(tc + 16) * QSTR + d0];
            float4 b2 = *(float4*)&Ks[(tc + 32) * QSTR + d0];
            float4 b3 = *(float4*)&Ks[(tc + 48) * QSTR + d0];
            dot4acc(s[0][0], a0, b0); dot4acc(s[0][1], a0, b1);
            dot4acc(s[0][2], a0, b2); dot4acc(s[0][3], a0, b3);
            dot4acc(s[1][0], a1, b0); dot4acc(s[1][1], a1, b1);
            dot4acc(s[1][2], a1, b2); dot4acc(s[1][3], a1, b3);
            dot4acc(s[2][0], a2, b0); dot4acc(s[2][1], a2, b1);
            dot4acc(s[2][2], a2, b2); dot4acc(s[2][3], a2, b3);
            dot4acc(s[3][0], a3, b0); dot4acc(s[3][1], a3, b1);
            dot4acc(s[3][2], a3, b2); dot4acc(s[3][3], a3, b3);
        }

        // Online softmax per row (row owned by 16 tc-lanes of same tr group)
#pragma unroll
        for (int i = 0; i < 4; i++) {
            float mx = fmaxf(fmaxf(s[i][0], s[i][1]), fmaxf(s[i][2], s[i][3]));
#pragma unroll
            for (int off = 8; off >= 1; off >>= 1)
                mx = fmaxf(mx, __shfl_xor_sync(0xffffffffu, mx, off));
            float mnew = fmaxf(m_i[i], mx);
            float corr = __expf(m_i[i] - mnew);
            float rs = 0.f;
#pragma unroll
            for (int j = 0; j < 4; j++) {
                s[i][j] = __expf(s[i][j] - mnew);
                rs += s[i][j];
            }
#pragma unroll
            for (int off = 8; off >= 1; off >>= 1)
                rs += __shfl_xor_sync(0xffffffffu, rs, off);
            l_i[i] = l_i[i] * corr + rs;
            m_i[i] = mnew;
#pragma unroll
            for (int j = 0; j < 8; j++) o[i][j] *= corr;

            int prow = (tr * 4 + i) * PSTR;
            Ps[prow + tc +  0] = s[i][0];
            Ps[prow + tc + 16] = s[i][1];
            Ps[prow + tc + 32] = s[i][2];
            Ps[prow + tc + 48] = s[i][3];
        }
        __syncthreads();

        // O += P @ V   (inner dim 64; thread cols tc*8..tc*8+7)
#pragma unroll 4
        for (int kk0 = 0; kk0 < 64; kk0 += 4) {
            float pv[4][4];
#pragma unroll
            for (int i = 0; i < 4; i++) {
                float4 t = *(float4*)&Ps[(tr * 4 + i) * PSTR + kk0];
                pv[i][0] = t.x; pv[i][1] = t.y; pv[i][2] = t.z; pv[i][3] = t.w;
            }
#pragma unroll
            for (int kk = 0; kk < 4; kk++) {
                float4 v0 = *(float4*)&Vs[(kk0 + kk) * QSTR + tc * 8];
                float4 v1 = *(float4*)&Vs[(kk0 + kk) * QSTR + tc * 8 + 4];
#pragma unroll
                for (int i = 0; i < 4; i++) {
                    float p = pv[i][kk];
                    o[i][0] = fmaf(p, v0.x, o[i][0]);
                    o[i][1] = fmaf(p, v0.y, o[i][1]);
                    o[i][2] = fmaf(p, v0.z, o[i][2]);
                    o[i][3] = fmaf(p, v0.w, o[i][3]);
                    o[i][4] = fmaf(p, v1.x, o[i][4]);
                    o[i][5] = fmaf(p, v1.y, o[i][5]);
                    o[i][6] = fmaf(p, v1.z, o[i][6]);
                    o[i][7] = fmaf(p, v1.w, o[i][7]);
                }
            }
        }
    }

    // Epilogue: normalize, scatter to [B,S,DMODEL]
#pragma unroll
    for (int i = 0; i < 4; i++) {
        float inv = 1.0f / l_i[i];
        int row = q0 + tr * 4 + i;
        float* op = O + ((size_t)(b * SEQ + row)) * DMODEL + h * DKK + tc * 8;
        float4 o0 = make_float4(o[i][0] * inv, o[i][1] * inv, o[i][2] * inv, o[i][3] * inv);
        float4 o1 = make_float4(o[i][4] * inv, o[i][5] * inv, o[i][6] * inv, o[i][7] * inv);
        *(float4*)op = o0;
        *(float4*)(op + 4) = o1;
    }
}

// ---------------------------------------------------------------------------
// Launch: Q/K/V projections -> flash attention -> output projection.
// K/V projections write directly into d_out's cache regions (also the
// attention inputs). d_out layout: [out | K_cache | V_cache].
// ---------------------------------------------------------------------------
extern "C" void kernel_launch(void* const* d_in, const int* in_sizes, int n_in,
                              void* d_out, int out_size)
{
    const float* x   = (const float*)d_in[0];
    const float* W_q = (const float*)d_in[1];
    const float* b_q = (const float*)d_in[2];
    const float* W_k = (const float*)d_in[3];
    const float* b_k = (const float*)d_in[4];
    const float* W_v = (const float*)d_in[5];
    const float* b_v = (const float*)d_in[6];
    const float* W_o = (const float*)d_in[7];
    const float* b_o = (const float*)d_in[8];

    float* out = (float*)d_out;
    float* Kc  = out + (size_t)BATCH * SEQ * DMODEL;           // 8388608
    float* Vc  = Kc  + (size_t)BATCH * SEQ * DKK;              // +524288

    float* qbuf = nullptr;
    float* abuf = nullptr;
    cudaGetSymbolAddress((void**)&qbuf, g_q);
    cudaGetSymbolAddress((void**)&abuf, g_attn);

    cudaFuncSetAttribute(flash_kernel,
                         cudaFuncAttributeMaxDynamicSharedMemorySize,
                         FLASH_SMEM_BYTES);

    const int M = BATCH * SEQ;  // 4096

    // Q projection: [4096,2048] @ [2048,2048]
    sgemm_bias_kernel<<<dim3(DMODEL / 128, M / 128), 256>>>(
        x, W_q, b_q, qbuf, M, DMODEL, DMODEL);
    // K projection: [4096,2048] @ [2048,128] -> K_cache
    sgemm_bias_kernel<<<dim3(1, M / 128), 256>>>(
        x, W_k, b_k, Kc, M, DKK, DMODEL);
    // V projection -> V_cache
    sgemm_bias_kernel<<<dim3(1, M / 128), 256>>>(
        x, W_v, b_v, Vc, M, DKK, DMODEL);

    // Flash attention: grid (q_tiles, heads, batch)
    flash_kernel<<<dim3(SEQ / 64, NHEADS, BATCH), 256, FLASH_SMEM_BYTES>>>(
        qbuf, Kc, Vc, abuf);

    // Output projection: [4096,2048] @ [2048,2048] -> out
    sgemm_bias_kernel<<<dim3(DMODEL / 128, M / 128), 256>>>(
        abuf, W_o, b_o, out, M, DMODEL, DMODEL);
}

// round 2
// speedup vs baseline: 1.6564x; 1.6564x over previous
#include <cuda_runtime.h>

#define BATCH  2
#define SEQ    2048
#define DMODEL 2048
#define NHEADS 16
#define DKK    128

// Scratch (allocation-free rule: device globals)
__device__ float g_q[BATCH * SEQ * DMODEL];     // Q projection [B,S,DMODEL]
__device__ float g_attn[BATCH * SEQ * DMODEL];  // attention out [B,S,DMODEL]

// round-to-nearest tf32 (keep as float bit pattern)
__device__ __forceinline__ float f2tf(float x) {
    unsigned u;
    asm("cvt.rna.tf32.f32 %0, %1;" : "=r"(u) : "f"(x));
    return __uint_as_float(u);
}

// m16n8k8 tf32 mma: D += A(16x8 row) * B(8x8 col)
__device__ __forceinline__ void mma8(float* c, const float4 a, const float b0, const float b1) {
    asm volatile(
        "mma.sync.aligned.m16n8k8.row.col.f32.tf32.tf32.f32 "
        "{%0,%1,%2,%3}, {%4,%5,%6,%7}, {%8,%9}, {%0,%1,%2,%3};\n"
        : "+f"(c[0]), "+f"(c[1]), "+f"(c[2]), "+f"(c[3])
        : "r"(__float_as_uint(a.x)), "r"(__float_as_uint(a.y)),
          "r"(__float_as_uint(a.z)), "r"(__float_as_uint(a.w)),
          "r"(__float_as_uint(b0)), "r"(__float_as_uint(b1)));
}

// ---------------------------------------------------------------------------
// tf32 tensor-core GEMM: C[M,N] = A[M,K] @ W[K,N] + bias
// BM=128 BN=128 BK=32, 256 thr (8 warps, 4x2), warp tile 32x64.
// Smem tiles stored in mma-fragment-permuted layout -> all frag loads LDS.128.
// ---------------------------------------------------------------------------
__global__ __launch_bounds__(256) void gemm_tf32(
    const float* __restrict__ A, const float* __restrict__ W,
    const float* __restrict__ bias, float* __restrict__ C,
    int M, int N, int K)
{
    __shared__ float AsP[4096];   // blocks (s:4, mt:8) x lane x 4 regs
    __shared__ float BsP[4096];   // blocks (s:4, np:8) x lane x 4 regs

    const int tid  = threadIdx.x;
    const int lane = tid & 31;
    const int wid  = tid >> 5;
    const int wm   = wid >> 1;        // 0..3
    const int wn   = wid & 1;         // 0..1
    const int rowBase = blockIdx.y * 128;
    const int colBase = blockIdx.x * 128;

    float acc[2][8][4];
#pragma unroll
    for (int i = 0; i < 2; i++)
#pragma unroll
        for (int j = 0; j < 8; j++)
#pragma unroll
            for (int r = 0; r < 4; r++) acc[i][j][r] = 0.f;

    const float* Aptr = A + (size_t)rowBase * K;
    const float* Wptr = W + colBase;

    float4 aR[4], bR[4];
#pragma unroll
    for (int t = 0; t < 4; t++) {
        int idx = tid + 256 * t;
        aR[t] = *(const float4*)(Aptr + (size_t)(idx >> 3) * K + 4 * (idx & 7));
        bR[t] = *(const float4*)(Wptr + (size_t)(idx >> 5) * N + 4 * (idx & 31));
    }

    for (int k0 = 0; k0 < K; k0 += 32) {
        __syncthreads();
        // A -> AsP (permuted, cvt to tf32)
#pragma unroll
        for (int t = 0; t < 4; t++) {
            int idx = tid + 256 * t;
            int r = idx >> 3, cb = idx & 7;
            int s = cb >> 1, h = cb & 1;
            int base = ((s * 8 + (r >> 4)) * 32 + (r & 7) * 4) * 4 + ((r >> 3) & 1) + 2 * h;
            AsP[base + 0]  = f2tf(aR[t].x);
            AsP[base + 4]  = f2tf(aR[t].y);
            AsP[base + 8]  = f2tf(aR[t].z);
            AsP[base + 12] = f2tf(aR[t].w);
        }
        // W -> BsP
#pragma unroll
        for (int t = 0; t < 4; t++) {
            int idx = tid + 256 * t;
            int kr = idx >> 5, cb = idx & 31;
            int s = kr >> 3, q = kr & 3, hB = (kr >> 2) & 1;
            int np = cb >> 2;
            int reg = ((cb >> 1) & 1) * 2 + hB;
            int lb = 16 * (cb & 1) + q;           // lane' = lb + 4*i
            int base = ((s * 8 + np) * 32) * 4 + lb * 4 + reg;
            BsP[base + 0]  = f2tf(bR[t].x);
            BsP[base + 16] = f2tf(bR[t].y);
            BsP[base + 32] = f2tf(bR[t].z);
            BsP[base + 48] = f2tf(bR[t].w);
        }
        __syncthreads();

        if (k0 + 32 < K) {
#pragma unroll
            for (int t = 0; t < 4; t++) {
                int idx = tid + 256 * t;
                aR[t] = *(const float4*)(Aptr + (size_t)(idx >> 3) * K + k0 + 32 + 4 * (idx & 7));
                bR[t] = *(const float4*)(Wptr + (size_t)(idx >> 5) * N + (size_t)(k0 + 32) * N + 4 * (idx & 31));
            }
        }

#pragma unroll
        for (int s = 0; s < 4; s++) {
            float4 af0 = *(const float4*)&AsP[((s * 8 + wm * 2 + 0) * 32 + lane) * 4];
            float4 af1 = *(const float4*)&AsP[((s * 8 + wm * 2 + 1) * 32 + lane) * 4];
#pragma unroll
            for (int npl = 0; npl < 4; npl++) {
                float4 bf = *(const float4*)&BsP[((s * 8 + wn * 4 + npl) * 32 + lane) * 4];
                mma8(acc[0][2 * npl],     af0, bf.x, bf.y);
                mma8(acc[0][2 * npl + 1], af0, bf.z, bf.w);
                mma8(acc[1][2 * npl],     af1, bf.x, bf.y);
                mma8(acc[1][2 * npl + 1], af1, bf.z, bf.w);
            }
        }
    }

    // epilogue + bias
    const int g = lane >> 2, q = lane & 3;
#pragma unroll
    for (int mt = 0; mt < 2; mt++) {
        int row0 = rowBase + wm * 32 + mt * 16 + g;
#pragma unroll
        for (int nt = 0; nt < 8; nt++) {
            int col = colBase + wn * 64 + nt * 8 + 2 * q;
            float b0 = bias[col], b1 = bias[col + 1];
            *(float2*)(C + (size_t)row0 * N + col) =
                make_float2(acc[mt][nt][0] + b0, acc[mt][nt][1] + b1);
            *(float2*)(C + (size_t)(row0 + 8) * N + col) =
                make_float2(acc[mt][nt][2] + b0, acc[mt][nt][3] + b1);
        }
    }
}

// ---------------------------------------------------------------------------
// tf32 tensor-core flash attention (MQA): CTA = (b,h,128 q-rows), 8 warps,
// warp = 16 rows. BK=64 keys/tile, D=128. Online softmax warp-local.
// Q held permuted in smem; K/V staged via registers (overlaps LDG w/ compute).
// ---------------------------------------------------------------------------
#define FLASH_SMEM_BYTES (40960 * 4)

__global__ __launch_bounds__(256) void flash_tf32(
    const float* __restrict__ Q, const float* __restrict__ Kc,
    const float* __restrict__ Vc, float* __restrict__ O)
{
    extern __shared__ float sm[];
    float* Qs = sm;            // 16384: blocks (w:8, s:16) x lane x 4
    float* Ks = sm + 16384;    //  8192: blocks (s:16, np:4) x lane x 4
    float* Vs = sm + 24576;    //  8192: blocks (s2:8, np2:8) x lane x 4
    float* Ps = sm + 32768;    //  8192: blocks (w:8, s2:8) x lane x 4

    const int tid  = threadIdx.x;
    const int lane = tid & 31;
    const int wid  = tid >> 5;
    const int h  = blockIdx.y;
    const int b  = blockIdx.z;
    const int q0 = blockIdx.x * 128;
    const float scale = 0.08838834764831845f;  // 1/sqrt(128)

    // fill Qs (pre-scaled, tf32)
    const float* Qg = Q + ((size_t)(b * SEQ + q0)) * DMODEL + h * DKK;
#pragma unroll
    for (int t = 0; t < 16; t++) {
        int idx = tid + 256 * t;
        int r = idx >> 5, cb = idx & 31;
        float4 v = *(const float4*)(Qg + (size_t)r * DMODEL + 4 * cb);
        int s = cb >> 1;
        int base = (((r >> 4) * 16 + s) * 32 + (r & 7) * 4) * 4 + ((r >> 3) & 1) + 2 * (cb & 1);
        Qs[base + 0]  = f2tf(v.x * scale);
        Qs[base + 4]  = f2tf(v.y * scale);
        Qs[base + 8]  = f2tf(v.z * scale);
        Qs[base + 12] = f2tf(v.w * scale);
    }

    const float* Kg = Kc + (size_t)b * SEQ * DKK;
    const float* Vg = Vc + (size_t)b * SEQ * DKK;

    float4 kreg[8], vreg[8];
#pragma unroll
    for (int t = 0; t < 8; t++) {
        int idx = tid + 256 * t;
        kreg[t] = *(const float4*)(Kg + (size_t)(idx >> 5) * DKK + 4 * (idx & 31));
    }

    float Oa[16][4];
#pragma unroll
    for (int i = 0; i < 16; i++)
#pragma unroll
        for (int r = 0; r < 4; r++) Oa[i][r] = 0.f;
    float m0 = -1e30f, m1 = -1e30f, l0 = 0.f, l1 = 0.f;

    for (int kt = 0; kt < SEQ / 64; kt++) {
        // stage K tile into smem (perm + cvt)
#pragma unroll
        for (int t = 0; t < 8; t++) {
            int idx = tid + 256 * t;
            int n = idx >> 5, cb = idx & 31;
            int s = cb >> 1, hh = cb & 1;
            int base = ((s * 4 + (n >> 4)) * 32 + (n & 7) * 4) * 4 + ((n >> 3) & 1) * 2 + hh;
            Ks[base + 0]  = f2tf(kreg[t].x);
            Ks[base + 4]  = f2tf(kreg[t].y);
            Ks[base + 8]  = f2tf(kreg[t].z);
            Ks[base + 12] = f2tf(kreg[t].w);
        }
        // start V loads (consumed after softmax)
        const float* Vt = Vg + (size_t)(kt * 64) * DKK;
#pragma unroll
        for (int t = 0; t < 8; t++) {
            int idx = tid + 256 * t;
            vreg[t] = *(const float4*)(Vt + (size_t)(idx >> 5) * DKK + 4 * (idx & 31));
        }
        __syncthreads();

        // S = Q @ K^T
        float sC[8][4];
#pragma unroll
        for (int i = 0; i < 8; i++)
#pragma unroll
            for (int r = 0; r < 4; r++) sC[i][r] = 0.f;
#pragma unroll
        for (int ss = 0; ss < 16; ss++) {
            float4 qa = *(const float4*)&Qs[((wid * 16 + ss) * 32 + lane) * 4];
#pragma unroll
            for (int np = 0; np < 4; np++) {
                float4 kb = *(const float4*)&Ks[((ss * 4 + np) * 32 + lane) * 4];
                mma8(sC[2 * np],     qa, kb.x, kb.y);
                mma8(sC[2 * np + 1], qa, kb.z, kb.w);
            }
        }

        // online softmax (rows g and g+8, quad-local)
        float mx0 = -1e30f, mx1 = -1e30f;
#pragma unroll
        for (int nt = 0; nt < 8; nt++) {
            mx0 = fmaxf(mx0, fmaxf(sC[nt][0], sC[nt][1]));
            mx1 = fmaxf(mx1, fmaxf(sC[nt][2], sC[nt][3]));
        }
        mx0 = fmaxf(mx0, __shfl_xor_sync(0xffffffffu, mx0, 1));
        mx0 = fmaxf(mx0, __shfl_xor_sync(0xffffffffu, mx0, 2));
        mx1 = fmaxf(mx1, __shfl_xor_sync(0xffffffffu, mx1, 1));
        mx1 = fmaxf(mx1, __shfl_xor_sync(0xffffffffu, mx1, 2));
        float mn0 = fmaxf(m0, mx0), mn1 = fmaxf(m1, mx1);
        float cr0 = __expf(m0 - mn0), cr1 = __expf(m1 - mn1);
        m0 = mn0; m1 = mn1;
        float rs0 = 0.f, rs1 = 0.f;
#pragma unroll
        for (int nt = 0; nt < 8; nt++) {
            sC[nt][0] = __expf(sC[nt][0] - mn0);
            sC[nt][1] = __expf(sC[nt][1] - mn0);
            sC[nt][2] = __expf(sC[nt][2] - mn1);
            sC[nt][3] = __expf(sC[nt][3] - mn1);
            rs0 += sC[nt][0] + sC[nt][1];
            rs1 += sC[nt][2] + sC[nt][3];
        }
        rs0 += __shfl_xor_sync(0xffffffffu, rs0, 1);
        rs0 += __shfl_xor_sync(0xffffffffu, rs0, 2);
        rs1 += __shfl_xor_sync(0xffffffffu, rs1, 1);
        rs1 += __shfl_xor_sync(0xffffffffu, rs1, 2);
        l0 = l0 * cr0 + rs0;
        l1 = l1 * cr1 + rs1;
#pragma unroll
        for (int nt2 = 0; nt2 < 16; nt2++) {
            Oa[nt2][0] *= cr0; Oa[nt2][1] *= cr0;
            Oa[nt2][2] *= cr1; Oa[nt2][3] *= cr1;
        }

        // stage V tile into smem (perm + cvt)
#pragma unroll
        for (int t = 0; t < 8; t++) {
            int idx = tid + 256 * t;
            int kk = idx >> 5, cb = idx & 31;
            int s2 = kk >> 3, np2 = cb >> 2;
            int reg = ((cb >> 1) & 1) * 2 + ((kk >> 2) & 1);
            int lb = 16 * (cb & 1) + (kk & 3);
            int base = ((s2 * 8 + np2) * 32) * 4 + lb * 4 + reg;
            Vs[base + 0]  = f2tf(vreg[t].x);
            Vs[base + 16] = f2tf(vreg[t].y);
            Vs[base + 32] = f2tf(vreg[t].z);
            Vs[base + 48] = f2tf(vreg[t].w);
        }
        // P (C-frag) -> Ps (A-frag perm), tf32
        {
            int g = lane >> 2, q = lane & 3;
            int lq = (g << 2) + ((q & 1) << 1);
            int h2 = q >> 1;
#pragma unroll
            for (int nt = 0; nt < 8; nt++) {
                int base = ((wid * 8 + nt) * 32) * 4 + 2 * h2;
                *(float2*)&Ps[base + lq * 4] =
                    make_float2(f2tf(sC[nt][0]), f2tf(sC[nt][2]));
                *(float2*)&Ps[base + (lq + 1) * 4] =
                    make_float2(f2tf(sC[nt][1]), f2tf(sC[nt][3]));
            }
        }
        // prefetch next K tile
        if (kt + 1 < SEQ / 64) {
            const float* Ktn = Kg + (size_t)((kt + 1) * 64) * DKK;
#pragma unroll
            for (int t = 0; t < 8; t++) {
                int idx = tid + 256 * t;
                kreg[t] = *(const float4*)(Ktn + (size_t)(idx >> 5) * DKK + 4 * (idx & 31));
            }
        }
        __syncthreads();

        // O += P @ V
#pragma unroll
        for (int s2 = 0; s2 < 8; s2++) {
            float4 pa = *(const float4*)&Ps[((wid * 8 + s2) * 32 + lane) * 4];
#pragma unroll
            for (int np2 = 0; np2 < 8; np2++) {
                float4 vb = *(const float4*)&Vs[((s2 * 8 + np2) * 32 + lane) * 4];
                mma8(Oa[2 * np2],     pa, vb.x, vb.y);
                mma8(Oa[2 * np2 + 1], pa, vb.z, vb.w);
            }
        }
    }

    // epilogue: normalize + scatter
    float inv0 = 1.f / l0, inv1 = 1.f / l1;
    int g = lane >> 2, q = lane & 3;
    int row0 = q0 + wid * 16 + g;
    float* Op = O + ((size_t)(b * SEQ + row0)) * DMODEL + h * DKK;
#pragma unroll
    for (int nt2 = 0; nt2 < 16; nt2++) {
        int col = nt2 * 8 + 2 * q;
        *(float2*)(Op + col) = make_float2(Oa[nt2][0] * inv0, Oa[nt2][1] * inv0);
        *(float2*)(Op + (size_t)8 * DMODEL + col) =
            make_float2(Oa[nt2][2] * inv1, Oa[nt2][3] * inv1);
    }
}

// ---------------------------------------------------------------------------
extern "C" void kernel_launch(void* const* d_in, const int* in_sizes, int n_in,
                              void* d_out, int out_size)
{
    const float* x   = (const float*)d_in[0];
    const float* W_q = (const float*)d_in[1];
    const float* b_q = (const float*)d_in[2];
    const float* W_k = (const float*)d_in[3];
    const float* b_k = (const float*)d_in[4];
    const float* W_v = (const float*)d_in[5];
    const float* b_v = (const float*)d_in[6];
    const float* W_o = (const float*)d_in[7];
    const float* b_o = (const float*)d_in[8];

    float* out = (float*)d_out;
    float* Kc  = out + (size_t)BATCH * SEQ * DMODEL;
    float* Vc  = Kc  + (size_t)BATCH * SEQ * DKK;

    float* qbuf = nullptr;
    float* abuf = nullptr;
    cudaGetSymbolAddress((void**)&qbuf, g_q);
    cudaGetSymbolAddress((void**)&abuf, g_attn);

    cudaFuncSetAttribute(flash_tf32,
                         cudaFuncAttributeMaxDynamicSharedMemorySize,
                         FLASH_SMEM_BYTES);

    const int M = BATCH * SEQ;  // 4096

    gemm_tf32<<<dim3(DMODEL / 128, M / 128), 256>>>(x, W_q, b_q, qbuf, M, DMODEL, DMODEL);
    gemm_tf32<<<dim3(1, M / 128), 256>>>(x, W_k, b_k, Kc, M, DKK, DMODEL);
    gemm_tf32<<<dim3(1, M / 128), 256>>>(x, W_v, b_v, Vc, M, DKK, DMODEL);

    flash_tf32<<<dim3(SEQ / 128, NHEADS, BATCH), 256, FLASH_SMEM_BYTES>>>(qbuf, Kc, Vc, abuf);

    gemm_tf32<<<dim3(DMODEL / 128, M / 128), 256>>>(abuf, W_o, b_o, out, M, DMODEL, DMODEL);
}

// round 5
// speedup vs baseline: 7.1242x; 4.3009x over previous
#include <cuda_runtime.h>
#include <cuda_fp16.h>
#include <cstdint>

#define BATCH  2
#define SEQ    2048
#define DMODEL 2048
#define NHEADS 16
#define DKK    128
#define MTOT   (BATCH * SEQ)

// Scratch (allocation-free rule: device globals)
__device__ __half g_xh [(size_t)MTOT * DMODEL];
__device__ __half g_wqh[(size_t)DMODEL * DMODEL];
__device__ __half g_wkh[(size_t)DMODEL * DKK];
__device__ __half g_wvh[(size_t)DMODEL * DKK];
__device__ __half g_woh[(size_t)DMODEL * DMODEL];
__device__ __half g_qh [(size_t)MTOT * DMODEL];   // Q proj, scaled, fp16
__device__ __half g_kh [(size_t)MTOT * DKK];      // K proj fp16
__device__ __half g_vh [(size_t)MTOT * DKK];      // V proj fp16
__device__ __half g_ah [(size_t)MTOT * DMODEL];   // attention out fp16

// ---------------------------------------------------------------------------
// helpers
// ---------------------------------------------------------------------------
__device__ __forceinline__ uint32_t smem_u32(const void* p) {
    uint32_t a;
    asm("{ .reg .u64 t; cvta.to.shared.u64 t, %1; cvt.u32.u64 %0, t; }" : "=r"(a) : "l"(p));
    return a;
}
#define CP16(dst, src) \
    asm volatile("cp.async.cg.shared.global [%0], [%1], 16;" :: "r"(dst), "l"(src) : "memory")
#define CPCOMMIT() asm volatile("cp.async.commit_group;" ::: "memory")
#define CPWAIT(n)  asm volatile("cp.async.wait_group %0;" :: "n"(n) : "memory")

__device__ __forceinline__ void ldsm4(uint32_t* r, uint32_t a) {
    asm volatile("ldmatrix.sync.aligned.m8n8.x4.shared.b16 {%0,%1,%2,%3}, [%4];"
                 : "=r"(r[0]), "=r"(r[1]), "=r"(r[2]), "=r"(r[3]) : "r"(a));
}
__device__ __forceinline__ void ldsm4t(uint32_t* r, uint32_t a) {
    asm volatile("ldmatrix.sync.aligned.m8n8.x4.trans.shared.b16 {%0,%1,%2,%3}, [%4];"
                 : "=r"(r[0]), "=r"(r[1]), "=r"(r[2]), "=r"(r[3]) : "r"(a));
}
// D(fp32) += A(fp16 16x16) * B(fp16 16x8)
__device__ __forceinline__ void mma16816(float* d, const uint32_t* a, const uint32_t* b) {
    asm volatile(
        "mma.sync.aligned.m16n8k16.row.col.f32.f16.f16.f32 "
        "{%0,%1,%2,%3},{%4,%5,%6,%7},{%8,%9},{%0,%1,%2,%3};"
        : "+f"(d[0]), "+f"(d[1]), "+f"(d[2]), "+f"(d[3])
        : "r"(a[0]), "r"(a[1]), "r"(a[2]), "r"(a[3]), "r"(b[0]), "r"(b[1]));
}
// variant with explicit b regs (for non-trans B pairing {r0,r2},{r1,r3})
__device__ __forceinline__ void mma16816b(float* d, const uint32_t* a,
                                          uint32_t b0, uint32_t b1) {
    asm volatile(
        "mma.sync.aligned.m16n8k16.row.col.f32.f16.f16.f32 "
        "{%0,%1,%2,%3},{%4,%5,%6,%7},{%8,%9},{%0,%1,%2,%3};"
        : "+f"(d[0]), "+f"(d[1]), "+f"(d[2]), "+f"(d[3])
        : "r"(a[0]), "r"(a[1]), "r"(a[2]), "r"(a[3]), "r"(b0), "r"(b1));
}
__device__ __forceinline__ uint32_t packh2(float lo, float hi) {
    __half2 h = __floats2half2_rn(lo, hi);
    return *(uint32_t*)&h;
}

// ---------------------------------------------------------------------------
// fp32 -> fp16 elementwise
// ---------------------------------------------------------------------------
__global__ __launch_bounds__(256) void f2h_kernel(
    const float* __restrict__ s, __half* __restrict__ d, int n)
{
    int i = (blockIdx.x * 256 + threadIdx.x) * 4;
    if (i < n) {
        float4 v = *(const float4*)(s + i);
        __half2* dp = (__half2*)(d + i);
        dp[0] = __floats2half2_rn(v.x, v.y);
        dp[1] = __floats2half2_rn(v.z, v.w);
    }
}

// ---------------------------------------------------------------------------
// fp16 tensor-core GEMM: C[M,N] = A[M,K] @ W[K,N] + bias
// BM=128 BN=128 BK=32, PIPE=3 cp.async stages, 256 thr (8 warps, 4x2),
// warp tile 32x64, ldmatrix fragments, mma.sync.m16n8k16.
// SPLIT: blockIdx.x selects operand-set 0/1 (fused K+V projections).
// ---------------------------------------------------------------------------
#define GS_A 10240            // 128 rows * 80B (32 halves padded to 80B)
#define GS_B 8704             // 32 rows * 272B (128 halves padded)
#define GS_STAGE (GS_A + GS_B)
#define GEMM_SMEM (3 * GS_STAGE)

template <bool WF32, bool WF16, bool SPLIT>
__global__ __launch_bounds__(256) void gemm_h(
    const __half* __restrict__ A,
    const __half* __restrict__ B0, const float* __restrict__ bias0,
    float* __restrict__ C0, __half* __restrict__ Ch0,
    const __half* __restrict__ B1, const float* __restrict__ bias1,
    float* __restrict__ C1, __half* __restrict__ Ch1,
    int M, int N, int K, float hscale)
{
    extern __shared__ char smc[];
    const uint32_t sb = smem_u32(smc);

    const int tid  = threadIdx.x;
    const int lane = tid & 31;
    const int wid  = tid >> 5;
    const int wm   = wid >> 1;      // 0..3
    const int wn   = wid & 1;       // 0..1

    const __half* Bsel = (SPLIT && blockIdx.x) ? B1 : B0;
    const float* biasS = (SPLIT && blockIdx.x) ? bias1 : bias0;
    float* Cf          = (SPLIT && blockIdx.x) ? C1 : C0;
    __half* Chf        = (SPLIT && blockIdx.x) ? Ch1 : Ch0;
    const int colBase  = SPLIT ? 0 : blockIdx.x * 128;
    const int rowBase  = blockIdx.y * 128;
    const int NC = K / 32;

    // stage chunk c into pipeline slot s
    auto stage = [&](int c, int s) {
        const int k0 = c * 32;
        const uint32_t sA = sb + s * GS_STAGE;
        const uint32_t sB = sA + GS_A;
#pragma unroll
        for (int i = 0; i < 2; i++) {
            int ch = tid + 256 * i;
            int r = ch >> 2, kc = ch & 3;
            CP16(sA + r * 80 + kc * 16,
                 A + (size_t)(rowBase + r) * K + k0 + kc * 8);
        }
#pragma unroll
        for (int i = 0; i < 2; i++) {
            int ch = tid + 256 * i;
            int r = ch >> 4, nc = ch & 15;
            CP16(sB + r * 272 + nc * 16,
                 Bsel + (size_t)(k0 + r) * N + colBase + nc * 8);
        }
    };

    float acc[2][8][4];
#pragma unroll
    for (int a = 0; a < 2; a++)
#pragma unroll
        for (int b = 0; b < 8; b++)
#pragma unroll
            for (int r = 0; r < 4; r++) acc[a][b][r] = 0.f;

    stage(0, 0); CPCOMMIT();
    stage(1, 1); CPCOMMIT();

    const uint32_t aOff = (wm * 32 + (lane & 15)) * 80 + (lane >> 4) * 16;
    const uint32_t bRow = (lane & 15) * 272;
    const uint32_t bCol = (wn * 64 + 8 * (lane >> 4)) * 2;

    for (int c = 0; c < NC; c++) {
        CPWAIT(1);
        __syncthreads();
        if (c + 2 < NC) stage(c + 2, (c + 2) % 3);
        CPCOMMIT();

        const uint32_t sA = sb + (c % 3) * GS_STAGE;
        const uint32_t sB = sA + GS_A;
#pragma unroll
        for (int ks = 0; ks < 2; ks++) {
            uint32_t a0[4], a1[4];
            ldsm4(a0, sA + aOff + ks * 32);
            ldsm4(a1, sA + aOff + 16 * 80 + ks * 32);
#pragma unroll
            for (int nbp = 0; nbp < 4; nbp++) {
                uint32_t bf[4];
                ldsm4t(bf, sB + bRow + ks * 16 * 272 + bCol + nbp * 32);
                mma16816(acc[0][2 * nbp],     a0, bf);
                mma16816(acc[0][2 * nbp + 1], a0, bf + 2);
                mma16816(acc[1][2 * nbp],     a1, bf);
                mma16816(acc[1][2 * nbp + 1], a1, bf + 2);
            }
        }
    }

    // epilogue
    const int g = lane >> 2, q = lane & 3;
#pragma unroll
    for (int mb = 0; mb < 2; mb++) {
        int row = rowBase + wm * 32 + mb * 16 + g;
#pragma unroll
        for (int nb = 0; nb < 8; nb++) {
            int col = colBase + wn * 64 + nb * 8 + 2 * q;
            float b0 = biasS[col], b1 = biasS[col + 1];
            float v0 = acc[mb][nb][0] + b0, v1 = acc[mb][nb][1] + b1;
            float v2 = acc[mb][nb][2] + b0, v3 = acc[mb][nb][3] + b1;
            if (WF32) {
                *(float2*)(Cf + (size_t)row * N + col)       = make_float2(v0, v1);
                *(float2*)(Cf + (size_t)(row + 8) * N + col) = make_float2(v2, v3);
            }
            if (WF16) {
                *(__half2*)(Chf + (size_t)row * N + col) =
                    __floats2half2_rn(v0 * hscale, v1 * hscale);
                *(__half2*)(Chf + (size_t)(row + 8) * N + col) =
                    __floats2half2_rn(v2 * hscale, v3 * hscale);
            }
        }
    }
}

// ---------------------------------------------------------------------------
// fp16 flash attention (MQA): CTA = (b,h,128 q-rows), 8 warps x 16 rows,
// BK=64 keys/tile, D=128. Q frags persistent in regs; P converts C->A frag
// in registers; K/V via 3-deep cp.async ring; online softmax warp-local.
// ---------------------------------------------------------------------------
#define FQ_BYTES 34816                 // 128 rows * 272B
#define FK_BYTES 17408                 // 64 rows * 272B
#define FLASH_SMEM (FQ_BYTES + 6 * FK_BYTES)   // Q + 3xK + 3xV = 139264
#define NT (SEQ / 64)                  // 32 key tiles

__global__ __launch_bounds__(256) void flash_h(
    const __half* __restrict__ Qh, const __half* __restrict__ Kh,
    const __half* __restrict__ Vh, __half* __restrict__ Ah)
{
    extern __shared__ char smc[];
    const uint32_t sb = smem_u32(smc);
    const uint32_t sQ = sb;
    const uint32_t sK0 = sb + FQ_BYTES;
    const uint32_t sV0 = sb + FQ_BYTES + 3 * FK_BYTES;

    const int tid  = threadIdx.x;
    const int lane = tid & 31;
    const int wid  = tid >> 5;
    const int h  = blockIdx.y;
    const int b  = blockIdx.z;
    const int q0 = blockIdx.x * 128;
    const size_t kvbase = (size_t)b * SEQ;

    // stage K(t), V(t) into ring buffer t%3
    auto stageKV = [&](int t) {
        if (t < NT) {
            const uint32_t kb = sK0 + (t % 3) * FK_BYTES;
            const uint32_t vb = sV0 + (t % 3) * FK_BYTES;
            const size_t rowg = kvbase + (size_t)t * 64;
#pragma unroll
            for (int i = 0; i < 4; i++) {
                int ch = tid + 256 * i;
                int r = ch >> 4, nc = ch & 15;
                CP16(kb + r * 272 + nc * 16, Kh + (rowg + r) * DKK + nc * 8);
            }
#pragma unroll
            for (int i = 0; i < 4; i++) {
                int ch = tid + 256 * i;
                int r = ch >> 4, nc = ch & 15;
                CP16(vb + r * 272 + nc * 16, Vh + (rowg + r) * DKK + nc * 8);
            }
        }
    };

    // prologue: Q + K0,V0 as group 0; K1,V1 as group 1
#pragma unroll
    for (int i = 0; i < 8; i++) {
        int ch = tid + 256 * i;
        int r = ch >> 4, nc = ch & 15;
        CP16(sQ + r * 272 + nc * 16,
             Qh + (size_t)(b * SEQ + q0 + r) * DMODEL + h * DKK + nc * 8);
    }
    stageKV(0); CPCOMMIT();
    stageKV(1); CPCOMMIT();

    CPWAIT(1);          // group 0 (Q,K0,V0) complete
    __syncthreads();

    // persistent Q fragments: 8 kslices x 4 regs
    uint32_t qf[8][4];
    {
        const uint32_t qB = sQ + (wid * 16 + (lane & 15)) * 272 + (lane >> 4) * 16;
#pragma unroll
        for (int ks = 0; ks < 8; ks++) ldsm4(qf[ks], qB + ks * 32);
    }

    float oA[16][4];
#pragma unroll
    for (int i = 0; i < 16; i++)
#pragma unroll
        for (int r = 0; r < 4; r++) oA[i][r] = 0.f;
    float m0 = -1e30f, m1 = -1e30f, l0 = 0.f, l1 = 0.f;

    const uint32_t kOff = (lane & 15) * 272 + (lane >> 4) * 16;
    const uint32_t vRow = (lane & 15) * 272;
    const uint32_t vCol = (lane >> 4) * 16;

    for (int t = 0; t < NT; t++) {
        if (t > 0) {
            CPWAIT(1);            // group t complete (t+1 may be pending)
            __syncthreads();      // all warps done with buffers from t-1
        }
        stageKV(t + 2);
        CPCOMMIT();

        const uint32_t kB = sK0 + (t % 3) * FK_BYTES;
        const uint32_t vB = sV0 + (t % 3) * FK_BYTES;

        // S = Q @ K^T : 16 q-rows x 64 keys.
        // K loaded non-trans from [key][d] smem: ldmatrix x4 returns
        // r0=(n0-7,k0-7) r1=(n8-15,k0-7) r2=(n0-7,k8-15) r3=(n8-15,k8-15)
        // -> B-fragment pairs are {r0,r2} (keys 0-7) and {r1,r3} (keys 8-15).
        float sC[8][4];
#pragma unroll
        for (int i = 0; i < 8; i++)
#pragma unroll
            for (int r = 0; r < 4; r++) sC[i][r] = 0.f;
#pragma unroll
        for (int ks = 0; ks < 8; ks++) {
#pragma unroll
            for (int nbp = 0; nbp < 4; nbp++) {
                uint32_t bf[4];
                ldsm4(bf, kB + nbp * 16 * 272 + kOff + ks * 32);
                mma16816b(sC[2 * nbp],     qf[ks], bf[0], bf[2]);
                mma16816b(sC[2 * nbp + 1], qf[ks], bf[1], bf[3]);
            }
        }

        // online softmax: regs [0],[1] = row g; [2],[3] = row g+8
        float mx0 = -1e30f, mx1 = -1e30f;
#pragma unroll
        for (int nb = 0; nb < 8; nb++) {
            mx0 = fmaxf(mx0, fmaxf(sC[nb][0], sC[nb][1]));
            mx1 = fmaxf(mx1, fmaxf(sC[nb][2], sC[nb][3]));
        }
        mx0 = fmaxf(mx0, __shfl_xor_sync(0xffffffffu, mx0, 1));
        mx0 = fmaxf(mx0, __shfl_xor_sync(0xffffffffu, mx0, 2));
        mx1 = fmaxf(mx1, __shfl_xor_sync(0xffffffffu, mx1, 1));
        mx1 = fmaxf(mx1, __shfl_xor_sync(0xffffffffu, mx1, 2));
        float mn0 = fmaxf(m0, mx0), mn1 = fmaxf(m1, mx1);
        float cr0 = __expf(m0 - mn0), cr1 = __expf(m1 - mn1);
        m0 = mn0; m1 = mn1;
        float rs0 = 0.f, rs1 = 0.f;
#pragma unroll
        for (int nb = 0; nb < 8; nb++) {
            sC[nb][0] = __expf(sC[nb][0] - mn0);
            sC[nb][1] = __expf(sC[nb][1] - mn0);
            sC[nb][2] = __expf(sC[nb][2] - mn1);
            sC[nb][3] = __expf(sC[nb][3] - mn1);
            rs0 += sC[nb][0] + sC[nb][1];
            rs1 += sC[nb][2] + sC[nb][3];
        }
        rs0 += __shfl_xor_sync(0xffffffffu, rs0, 1);
        rs0 += __shfl_xor_sync(0xffffffffu, rs0, 2);
        rs1 += __shfl_xor_sync(0xffffffffu, rs1, 1);
        rs1 += __shfl_xor_sync(0xffffffffu, rs1, 2);
        l0 = l0 * cr0 + rs0;
        l1 = l1 * cr1 + rs1;
#pragma unroll
        for (int db = 0; db < 16; db++) {
            oA[db][0] *= cr0; oA[db][1] *= cr0;
            oA[db][2] *= cr1; oA[db][3] *= cr1;
        }

        // P: C-frag -> A-frag, in registers (fp16)
        uint32_t pf[4][4];
#pragma unroll
        for (int s = 0; s < 4; s++) {
            pf[s][0] = packh2(sC[2 * s][0],     sC[2 * s][1]);
            pf[s][1] = packh2(sC[2 * s][2],     sC[2 * s][3]);
            pf[s][2] = packh2(sC[2 * s + 1][0], sC[2 * s + 1][1]);
            pf[s][3] = packh2(sC[2 * s + 1][2], sC[2 * s + 1][3]);
        }

        // O += P @ V  (V trans-loaded: pairs {r0,r1},{r2,r3})
#pragma unroll
        for (int s = 0; s < 4; s++) {
#pragma unroll
            for (int dbp = 0; dbp < 8; dbp++) {
                uint32_t vf[4];
                ldsm4t(vf, vB + s * 16 * 272 + vRow + (dbp * 16) * 2 + vCol);
                mma16816(oA[2 * dbp],     pf[s], vf);
                mma16816(oA[2 * dbp + 1], pf[s], vf + 2);
            }
        }
    }

    // epilogue: normalize, write fp16 attention output
    const float inv0 = 1.f / l0, inv1 = 1.f / l1;
    const int g = lane >> 2, q = lane & 3;
    const int row = q0 + wid * 16 + g;
    __half* Op = Ah + (size_t)(b * SEQ + row) * DMODEL + h * DKK;
#pragma unroll
    for (int db = 0; db < 16; db++) {
        int col = db * 8 + 2 * q;
        *(__half2*)(Op + col) = __floats2half2_rn(oA[db][0] * inv0, oA[db][1] * inv0);
        *(__half2*)(Op + (size_t)8 * DMODEL + col) =
            __floats2half2_rn(oA[db][2] * inv1, oA[db][3] * inv1);
    }
}

// ---------------------------------------------------------------------------
extern "C" void kernel_launch(void* const* d_in, const int* in_sizes, int n_in,
                              void* d_out, int out_size)
{
    const float* x   = (const float*)d_in[0];
    const float* W_q = (const float*)d_in[1];
    const float* b_q = (const float*)d_in[2];
    const float* W_k = (const float*)d_in[3];
    const float* b_k = (const float*)d_in[4];
    const float* W_v = (const float*)d_in[5];
    const float* b_v = (const float*)d_in[6];
    const float* W_o = (const float*)d_in[7];
    const float* b_o = (const float*)d_in[8];

    float* out = (float*)d_out;
    float* Kc  = out + (size_t)MTOT * DMODEL;
    float* Vc  = Kc  + (size_t)MTOT * DKK;

    __half *xh, *wqh, *wkh, *wvh, *woh, *qh, *kh, *vh, *ah;
    cudaGetSymbolAddress((void**)&xh,  g_xh);
    cudaGetSymbolAddress((void**)&wqh, g_wqh);
    cudaGetSymbolAddress((void**)&wkh, g_wkh);
    cudaGetSymbolAddress((void**)&wvh, g_wvh);
    cudaGetSymbolAddress((void**)&woh, g_woh);
    cudaGetSymbolAddress((void**)&qh,  g_qh);
    cudaGetSymbolAddress((void**)&kh,  g_kh);
    cudaGetSymbolAddress((void**)&vh,  g_vh);
    cudaGetSymbolAddress((void**)&ah,  g_ah);

    cudaFuncSetAttribute(gemm_h<false, true, false>,
                         cudaFuncAttributeMaxDynamicSharedMemorySize, GEMM_SMEM);
    cudaFuncSetAttribute(gemm_h<true, true, true>,
                         cudaFuncAttributeMaxDynamicSharedMemorySize, GEMM_SMEM);
    cudaFuncSetAttribute(gemm_h<true, false, false>,
                         cudaFuncAttributeMaxDynamicSharedMemorySize, GEMM_SMEM);
    cudaFuncSetAttribute(flash_h,
                         cudaFuncAttributeMaxDynamicSharedMemorySize, FLASH_SMEM);

    // fp32 -> fp16 conversions
    f2h_kernel<<<(MTOT * DMODEL / 4 + 255) / 256, 256>>>(x, xh, MTOT * DMODEL);
    f2h_kernel<<<(DMODEL * DMODEL / 4 + 255) / 256, 256>>>(W_q, wqh, DMODEL * DMODEL);
    f2h_kernel<<<(DMODEL * DKK / 4 + 255) / 256, 256>>>(W_k, wkh, DMODEL * DKK);
    f2h_kernel<<<(DMODEL * DKK / 4 + 255) / 256, 256>>>(W_v, wvh, DMODEL * DKK);
    f2h_kernel<<<(DMODEL * DMODEL / 4 + 255) / 256, 256>>>(W_o, woh, DMODEL * DMODEL);

    const float qscale = 0.08838834764831845f;  // 1/sqrt(128)

    // Q projection -> qh (fp16, pre-scaled)
    gemm_h<false, true, false><<<dim3(DMODEL / 128, MTOT / 128), 256, GEMM_SMEM>>>(
        xh, wqh, b_q, nullptr, qh, nullptr, nullptr, nullptr, nullptr,
        MTOT, DMODEL, DMODEL, qscale);

    // K + V projections fused (grid.x selects): fp32 caches + fp16 copies
    gemm_h<true, true, true><<<dim3(2, MTOT / 128), 256, GEMM_SMEM>>>(
        xh, wkh, b_k, Kc, kh, wvh, b_v, Vc, vh,
        MTOT, DKK, DMODEL, 1.0f);

    // flash attention -> ah (fp16)
    flash_h<<<dim3(SEQ / 128, NHEADS, BATCH), 256, FLASH_SMEM>>>(qh, kh, vh, ah);

    // output projection -> out (fp32 + bias)
    gemm_h<true, false, false><<<dim3(DMODEL / 128, MTOT / 128), 256, GEMM_SMEM>>>(
        ah, woh, b_o, out, nullptr, nullptr, nullptr, nullptr, nullptr,
        MTOT, DMODEL, DMODEL, 1.0f);
}

// round 6
// speedup vs baseline: 7.9350x; 1.1138x over previous
#include <cuda_runtime.h>
#include <cuda_fp16.h>
#include <cstdint>

#define BATCH  2
#define SEQ    2048
#define DMODEL 2048
#define NHEADS 16
#define DKK    128
#define MTOT   (BATCH * SEQ)

#define N_X  ((size_t)MTOT * DMODEL)     // 8388608
#define N_WQ ((size_t)DMODEL * DMODEL)   // 4194304
#define N_WK ((size_t)DMODEL * DKK)      // 262144

// Scratch (allocation-free rule: device globals)
__device__ __half g_xh [N_X];
__device__ __half g_wqh[N_WQ];
__device__ __half g_wkh[N_WK];
__device__ __half g_wvh[N_WK];
__device__ __half g_woh[N_WQ];
__device__ __half g_qh [N_X];            // Q proj, scaled, fp16
__device__ __half g_kh [(size_t)MTOT * DKK];
__device__ __half g_vh [(size_t)MTOT * DKK];
__device__ __half g_ah [N_X];            // attention out fp16

// ---------------------------------------------------------------------------
// helpers
// ---------------------------------------------------------------------------
__device__ __forceinline__ uint32_t smem_u32(const void* p) {
    uint32_t a;
    asm("{ .reg .u64 t; cvta.to.shared.u64 t, %1; cvt.u32.u64 %0, t; }" : "=r"(a) : "l"(p));
    return a;
}
#define CP16(dst, src) \
    asm volatile("cp.async.cg.shared.global [%0], [%1], 16;" :: "r"(dst), "l"(src) : "memory")
#define CPCOMMIT() asm volatile("cp.async.commit_group;" ::: "memory")
#define CPWAIT(n)  asm volatile("cp.async.wait_group %0;" :: "n"(n) : "memory")

__device__ __forceinline__ void ldsm4(uint32_t* r, uint32_t a) {
    asm volatile("ldmatrix.sync.aligned.m8n8.x4.shared.b16 {%0,%1,%2,%3}, [%4];"
                 : "=r"(r[0]), "=r"(r[1]), "=r"(r[2]), "=r"(r[3]) : "r"(a));
}
__device__ __forceinline__ void ldsm4t(uint32_t* r, uint32_t a) {
    asm volatile("ldmatrix.sync.aligned.m8n8.x4.trans.shared.b16 {%0,%1,%2,%3}, [%4];"
                 : "=r"(r[0]), "=r"(r[1]), "=r"(r[2]), "=r"(r[3]) : "r"(a));
}
__device__ __forceinline__ void mma16816(float* d, const uint32_t* a, const uint32_t* b) {
    asm volatile(
        "mma.sync.aligned.m16n8k16.row.col.f32.f16.f16.f32 "
        "{%0,%1,%2,%3},{%4,%5,%6,%7},{%8,%9},{%0,%1,%2,%3};"
        : "+f"(d[0]), "+f"(d[1]), "+f"(d[2]), "+f"(d[3])
        : "r"(a[0]), "r"(a[1]), "r"(a[2]), "r"(a[3]), "r"(b[0]), "r"(b[1]));
}
__device__ __forceinline__ void mma16816b(float* d, const uint32_t* a,
                                          uint32_t b0, uint32_t b1) {
    asm volatile(
        "mma.sync.aligned.m16n8k16.row.col.f32.f16.f16.f32 "
        "{%0,%1,%2,%3},{%4,%5,%6,%7},{%8,%9},{%0,%1,%2,%3};"
        : "+f"(d[0]), "+f"(d[1]), "+f"(d[2]), "+f"(d[3])
        : "r"(a[0]), "r"(a[1]), "r"(a[2]), "r"(a[3]), "r"(b0), "r"(b1));
}
__device__ __forceinline__ uint32_t packh2(float lo, float hi) {
    __half2 h = __floats2half2_rn(lo, hi);
    return *(uint32_t*)&h;
}

// ---------------------------------------------------------------------------
// fused fp32 -> fp16: all five tensors in one launch (grid covers concat)
// ---------------------------------------------------------------------------
#define F2H_TOTAL (N_X + N_WQ + N_WK + N_WK + N_WQ)   // 17301504

__global__ __launch_bounds__(256) void f2h_all(
    const float* __restrict__ x,  const float* __restrict__ wq,
    const float* __restrict__ wk, const float* __restrict__ wv,
    const float* __restrict__ wo)
{
    size_t i = ((size_t)blockIdx.x * 256 + threadIdx.x) * 4;
    const float* s;
    __half* d;
    size_t off;
    if (i < N_X)                            { s = x;  d = g_xh;  off = i; }
    else if (i < N_X + N_WQ)                { s = wq; d = g_wqh; off = i - N_X; }
    else if (i < N_X + N_WQ + N_WK)         { s = wk; d = g_wkh; off = i - N_X - N_WQ; }
    else if (i < N_X + N_WQ + 2 * N_WK)     { s = wv; d = g_wvh; off = i - N_X - N_WQ - N_WK; }
    else                                    { s = wo; d = g_woh; off = i - N_X - N_WQ - 2 * N_WK; }
    float4 v = *(const float4*)(s + off);
    __half2* dp = (__half2*)(d + off);
    dp[0] = __floats2half2_rn(v.x, v.y);
    dp[1] = __floats2half2_rn(v.z, v.w);
}

// ---------------------------------------------------------------------------
// GEMM tile geometry (shared by both gemm kernels)
// BM=128 BN=128 BK=32, PIPE=3 cp.async stages, 256 thr (8 warps, 4x2),
// warp tile 32x64, ldmatrix fragments, mma.sync.m16n8k16.
// ---------------------------------------------------------------------------
#define GS_A 10240            // 128 rows * 80B (32 halves padded to 80B)
#define GS_B 8704             // 32 rows * 272B (128 halves padded)
#define GS_STAGE (GS_A + GS_B)
#define GEMM_SMEM (3 * GS_STAGE)

// ---------------------------------------------------------------------------
// Fused Q/K/V projection: grid.x 0..15 -> Q col-tiles; 16 -> K; 17 -> V.
// ---------------------------------------------------------------------------
__global__ __launch_bounds__(256, 2) void gemm_qkv(
    const __half* __restrict__ A,
    const float* __restrict__ b_q, const float* __restrict__ b_k,
    const float* __restrict__ b_v,
    float* __restrict__ Kc, float* __restrict__ Vc, float qscale)
{
    extern __shared__ char smc[];
    const uint32_t sb = smem_u32(smc);

    const int tid  = threadIdx.x;
    const int lane = tid & 31;
    const int wid  = tid >> 5;
    const int wm   = wid >> 1;
    const int wn   = wid & 1;
    const int bx   = blockIdx.x;
    const int K    = DMODEL;
    const int NC   = K / 32;
    const int rowBase = blockIdx.y * 128;

    const bool isQ = bx < 16;
    const bool isK = bx == 16;
    const __half* Bsel = isQ ? g_wqh : (isK ? g_wkh : g_wvh);
    const float* biasS = isQ ? b_q : (isK ? b_k : b_v);
    __half* Chf        = isQ ? g_qh : (isK ? g_kh : g_vh);
    float* Cf          = isK ? Kc : Vc;
    const int N        = isQ ? DMODEL : DKK;
    const int colBase  = isQ ? bx * 128 : 0;
    const float hscale = isQ ? qscale : 1.0f;

    auto stage = [&](int c, int s) {
        const int k0 = c * 32;
        const uint32_t sA = sb + s * GS_STAGE;
        const uint32_t sB = sA + GS_A;
#pragma unroll
        for (int i = 0; i < 2; i++) {
            int ch = tid + 256 * i;
            int r = ch >> 2, kc = ch & 3;
            CP16(sA + r * 80 + kc * 16, A + (size_t)(rowBase + r) * K + k0 + kc * 8);
        }
#pragma unroll
        for (int i = 0; i < 2; i++) {
            int ch = tid + 256 * i;
            int r = ch >> 4, nc = ch & 15;
            CP16(sB + r * 272 + nc * 16, Bsel + (size_t)(k0 + r) * N + colBase + nc * 8);
        }
    };

    float acc[2][8][4];
#pragma unroll
    for (int a = 0; a < 2; a++)
#pragma unroll
        for (int b = 0; b < 8; b++)
#pragma unroll
            for (int r = 0; r < 4; r++) acc[a][b][r] = 0.f;

    stage(0, 0); CPCOMMIT();
    stage(1, 1); CPCOMMIT();

    const uint32_t aOff = (wm * 32 + (lane & 15)) * 80 + (lane >> 4) * 16;
    const uint32_t bRow = (lane & 15) * 272;
    const uint32_t bCol = (wn * 64 + 8 * (lane >> 4)) * 2;

    for (int c = 0; c < NC; c++) {
        CPWAIT(1);
        __syncthreads();
        if (c + 2 < NC) stage(c + 2, (c + 2) % 3);
        CPCOMMIT();

        const uint32_t sA = sb + (c % 3) * GS_STAGE;
        const uint32_t sB = sA + GS_A;
#pragma unroll
        for (int ks = 0; ks < 2; ks++) {
            uint32_t a0[4], a1[4];
            ldsm4(a0, sA + aOff + ks * 32);
            ldsm4(a1, sA + aOff + 16 * 80 + ks * 32);
#pragma unroll
            for (int nbp = 0; nbp < 4; nbp++) {
                uint32_t bf[4];
                ldsm4t(bf, sB + bRow + ks * 16 * 272 + bCol + nbp * 32);
                mma16816(acc[0][2 * nbp],     a0, bf);
                mma16816(acc[0][2 * nbp + 1], a0, bf + 2);
                mma16816(acc[1][2 * nbp],     a1, bf);
                mma16816(acc[1][2 * nbp + 1], a1, bf + 2);
            }
        }
    }

    const int g = lane >> 2, q = lane & 3;
#pragma unroll
    for (int mb = 0; mb < 2; mb++) {
        int row = rowBase + wm * 32 + mb * 16 + g;
#pragma unroll
        for (int nb = 0; nb < 8; nb++) {
            int col = colBase + wn * 64 + nb * 8 + 2 * q;
            float b0 = biasS[col], b1 = biasS[col + 1];
            float v0 = acc[mb][nb][0] + b0, v1 = acc[mb][nb][1] + b1;
            float v2 = acc[mb][nb][2] + b0, v3 = acc[mb][nb][3] + b1;
            *(__half2*)(Chf + (size_t)row * N + col) =
                __floats2half2_rn(v0 * hscale, v1 * hscale);
            *(__half2*)(Chf + (size_t)(row + 8) * N + col) =
                __floats2half2_rn(v2 * hscale, v3 * hscale);
            if (!isQ) {
                *(float2*)(Cf + (size_t)row * N + col)       = make_float2(v0, v1);
                *(float2*)(Cf + (size_t)(row + 8) * N + col) = make_float2(v2, v3);
            }
        }
    }
}

// ---------------------------------------------------------------------------
// Output projection GEMM: out(fp32) = ah @ woh + b_o
// ---------------------------------------------------------------------------
__global__ __launch_bounds__(256, 2) void gemm_o(
    const __half* __restrict__ A, const float* __restrict__ bias,
    float* __restrict__ C)
{
    extern __shared__ char smc[];
    const uint32_t sb = smem_u32(smc);

    const int tid  = threadIdx.x;
    const int lane = tid & 31;
    const int wid  = tid >> 5;
    const int wm   = wid >> 1;
    const int wn   = wid & 1;
    const int N = DMODEL, K = DMODEL, NC = K / 32;
    const int rowBase = blockIdx.y * 128;
    const int colBase = blockIdx.x * 128;

    auto stage = [&](int c, int s) {
        const int k0 = c * 32;
        const uint32_t sA = sb + s * GS_STAGE;
        const uint32_t sB = sA + GS_A;
#pragma unroll
        for (int i = 0; i < 2; i++) {
            int ch = tid + 256 * i;
            int r = ch >> 2, kc = ch & 3;
            CP16(sA + r * 80 + kc * 16, A + (size_t)(rowBase + r) * K + k0 + kc * 8);
        }
#pragma unroll
        for (int i = 0; i < 2; i++) {
            int ch = tid + 256 * i;
            int r = ch >> 4, nc = ch & 15;
            CP16(sB + r * 272 + nc * 16, g_woh + (size_t)(k0 + r) * N + colBase + nc * 8);
        }
    };

    float acc[2][8][4];
#pragma unroll
    for (int a = 0; a < 2; a++)
#pragma unroll
        for (int b = 0; b < 8; b++)
#pragma unroll
            for (int r = 0; r < 4; r++) acc[a][b][r] = 0.f;

    stage(0, 0); CPCOMMIT();
    stage(1, 1); CPCOMMIT();

    const uint32_t aOff = (wm * 32 + (lane & 15)) * 80 + (lane >> 4) * 16;
    const uint32_t bRow = (lane & 15) * 272;
    const uint32_t bCol = (wn * 64 + 8 * (lane >> 4)) * 2;

    for (int c = 0; c < NC; c++) {
        CPWAIT(1);
        __syncthreads();
        if (c + 2 < NC) stage(c + 2, (c + 2) % 3);
        CPCOMMIT();

        const uint32_t sA = sb + (c % 3) * GS_STAGE;
        const uint32_t sB = sA + GS_A;
#pragma unroll
        for (int ks = 0; ks < 2; ks++) {
            uint32_t a0[4], a1[4];
            ldsm4(a0, sA + aOff + ks * 32);
            ldsm4(a1, sA + aOff + 16 * 80 + ks * 32);
#pragma unroll
            for (int nbp = 0; nbp < 4; nbp++) {
                uint32_t bf[4];
                ldsm4t(bf, sB + bRow + ks * 16 * 272 + bCol + nbp * 32);
                mma16816(acc[0][2 * nbp],     a0, bf);
                mma16816(acc[0][2 * nbp + 1], a0, bf + 2);
                mma16816(acc[1][2 * nbp],     a1, bf);
                mma16816(acc[1][2 * nbp + 1], a1, bf + 2);
            }
        }
    }

    const int g = lane >> 2, q = lane & 3;
#pragma unroll
    for (int mb = 0; mb < 2; mb++) {
        int row = rowBase + wm * 32 + mb * 16 + g;
#pragma unroll
        for (int nb = 0; nb < 8; nb++) {
            int col = colBase + wn * 64 + nb * 8 + 2 * q;
            float b0 = bias[col], b1 = bias[col + 1];
            *(float2*)(C + (size_t)row * N + col) =
                make_float2(acc[mb][nb][0] + b0, acc[mb][nb][1] + b1);
            *(float2*)(C + (size_t)(row + 8) * N + col) =
                make_float2(acc[mb][nb][2] + b0, acc[mb][nb][3] + b1);
        }
    }
}

// ---------------------------------------------------------------------------
// fp16 flash attention (MQA): CTA = (b,h,128 q-rows), 8 warps x 16 rows,
// BK=64 keys/tile, D=128. Q frags persistent in regs; P converts C->A frag
// in registers; K/V via 3-deep cp.async ring; online softmax warp-local.
// ---------------------------------------------------------------------------
#define FQ_BYTES 34816                 // 128 rows * 272B
#define FK_BYTES 17408                 // 64 rows * 272B
#define FLASH_SMEM (FQ_BYTES + 6 * FK_BYTES)   // 139264
#define NT (SEQ / 64)

__global__ __launch_bounds__(256) void flash_h(
    const __half* __restrict__ Qh, const __half* __restrict__ Kh,
    const __half* __restrict__ Vh, __half* __restrict__ Ah)
{
    extern __shared__ char smc[];
    const uint32_t sb = smem_u32(smc);
    const uint32_t sQ = sb;
    const uint32_t sK0 = sb + FQ_BYTES;
    const uint32_t sV0 = sb + FQ_BYTES + 3 * FK_BYTES;

    const int tid  = threadIdx.x;
    const int lane = tid & 31;
    const int wid  = tid >> 5;
    const int h  = blockIdx.y;
    const int b  = blockIdx.z;
    const int q0 = blockIdx.x * 128;
    const size_t kvbase = (size_t)b * SEQ;

    auto stageKV = [&](int t) {
        if (t < NT) {
            const uint32_t kb = sK0 + (t % 3) * FK_BYTES;
            const uint32_t vb = sV0 + (t % 3) * FK_BYTES;
            const size_t rowg = kvbase + (size_t)t * 64;
#pragma unroll
            for (int i = 0; i < 4; i++) {
                int ch = tid + 256 * i;
                int r = ch >> 4, nc = ch & 15;
                CP16(kb + r * 272 + nc * 16, Kh + (rowg + r) * DKK + nc * 8);
            }
#pragma unroll
            for (int i = 0; i < 4; i++) {
                int ch = tid + 256 * i;
                int r = ch >> 4, nc = ch & 15;
                CP16(vb + r * 272 + nc * 16, Vh + (rowg + r) * DKK + nc * 8);
            }
        }
    };

#pragma unroll
    for (int i = 0; i < 8; i++) {
        int ch = tid + 256 * i;
        int r = ch >> 4, nc = ch & 15;
        CP16(sQ + r * 272 + nc * 16,
             Qh + (size_t)(b * SEQ + q0 + r) * DMODEL + h * DKK + nc * 8);
    }
    stageKV(0); CPCOMMIT();
    stageKV(1); CPCOMMIT();

    CPWAIT(1);
    __syncthreads();

    uint32_t qf[8][4];
    {
        const uint32_t qB = sQ + (wid * 16 + (lane & 15)) * 272 + (lane >> 4) * 16;
#pragma unroll
        for (int ks = 0; ks < 8; ks++) ldsm4(qf[ks], qB + ks * 32);
    }

    float oA[16][4];
#pragma unroll
    for (int i = 0; i < 16; i++)
#pragma unroll
        for (int r = 0; r < 4; r++) oA[i][r] = 0.f;
    float m0 = -1e30f, m1 = -1e30f, l0 = 0.f, l1 = 0.f;

    const uint32_t kOff = (lane & 15) * 272 + (lane >> 4) * 16;
    const uint32_t vRow = (lane & 15) * 272;
    const uint32_t vCol = (lane >> 4) * 16;

    for (int t = 0; t < NT; t++) {
        if (t > 0) {
            CPWAIT(1);
            __syncthreads();
        }
        stageKV(t + 2);
        CPCOMMIT();

        const uint32_t kB = sK0 + (t % 3) * FK_BYTES;
        const uint32_t vB = sV0 + (t % 3) * FK_BYTES;

        // S = Q @ K^T  (non-trans K: B-frag pairs {r0,r2},{r1,r3})
        float sC[8][4];
#pragma unroll
        for (int i = 0; i < 8; i++)
#pragma unroll
            for (int r = 0; r < 4; r++) sC[i][r] = 0.f;
#pragma unroll
        for (int ks = 0; ks < 8; ks++) {
#pragma unroll
            for (int nbp = 0; nbp < 4; nbp++) {
                uint32_t bf[4];
                ldsm4(bf, kB + nbp * 16 * 272 + kOff + ks * 32);
                mma16816b(sC[2 * nbp],     qf[ks], bf[0], bf[2]);
                mma16816b(sC[2 * nbp + 1], qf[ks], bf[1], bf[3]);
            }
        }

        float mx0 = -1e30f, mx1 = -1e30f;
#pragma unroll
        for (int nb = 0; nb < 8; nb++) {
            mx0 = fmaxf(mx0, fmaxf(sC[nb][0], sC[nb][1]));
            mx1 = fmaxf(mx1, fmaxf(sC[nb][2], sC[nb][3]));
        }
        mx0 = fmaxf(mx0, __shfl_xor_sync(0xffffffffu, mx0, 1));
        mx0 = fmaxf(mx0, __shfl_xor_sync(0xffffffffu, mx0, 2));
        mx1 = fmaxf(mx1, __shfl_xor_sync(0xffffffffu, mx1, 1));
        mx1 = fmaxf(mx1, __shfl_xor_sync(0xffffffffu, mx1, 2));
        float mn0 = fmaxf(m0, mx0), mn1 = fmaxf(m1, mx1);
        float cr0 = __expf(m0 - mn0), cr1 = __expf(m1 - mn1);
        m0 = mn0; m1 = mn1;
        float rs0 = 0.f, rs1 = 0.f;
#pragma unroll
        for (int nb = 0; nb < 8; nb++) {
            sC[nb][0] = __expf(sC[nb][0] - mn0);
            sC[nb][1] = __expf(sC[nb][1] - mn0);
            sC[nb][2] = __expf(sC[nb][2] - mn1);
            sC[nb][3] = __expf(sC[nb][3] - mn1);
            rs0 += sC[nb][0] + sC[nb][1];
            rs1 += sC[nb][2] + sC[nb][3];
        }
        rs0 += __shfl_xor_sync(0xffffffffu, rs0, 1);
        rs0 += __shfl_xor_sync(0xffffffffu, rs0, 2);
        rs1 += __shfl_xor_sync(0xffffffffu, rs1, 1);
        rs1 += __shfl_xor_sync(0xffffffffu, rs1, 2);
        l0 = l0 * cr0 + rs0;
        l1 = l1 * cr1 + rs1;
#pragma unroll
        for (int db = 0; db < 16; db++) {
            oA[db][0] *= cr0; oA[db][1] *= cr0;
            oA[db][2] *= cr1; oA[db][3] *= cr1;
        }

        uint32_t pf[4][4];
#pragma unroll
        for (int s = 0; s < 4; s++) {
            pf[s][0] = packh2(sC[2 * s][0],     sC[2 * s][1]);
            pf[s][1] = packh2(sC[2 * s][2],     sC[2 * s][3]);
            pf[s][2] = packh2(sC[2 * s + 1][0], sC[2 * s + 1][1]);
            pf[s][3] = packh2(sC[2 * s + 1][2], sC[2 * s + 1][3]);
        }

#pragma unroll
        for (int s = 0; s < 4; s++) {
#pragma unroll
            for (int dbp = 0; dbp < 8; dbp++) {
                uint32_t vf[4];
                ldsm4t(vf, vB + s * 16 * 272 + vRow + (dbp * 16) * 2 + vCol);
                mma16816(oA[2 * dbp],     pf[s], vf);
                mma16816(oA[2 * dbp + 1], pf[s], vf + 2);
            }
        }
    }

    const float inv0 = 1.f / l0, inv1 = 1.f / l1;
    const int g = lane >> 2, q = lane & 3;
    const int row = q0 + wid * 16 + g;
    __half* Op = Ah + (size_t)(b * SEQ + row) * DMODEL + h * DKK;
#pragma unroll
    for (int db = 0; db < 16; db++) {
        int col = db * 8 + 2 * q;
        *(__half2*)(Op + col) = __floats2half2_rn(oA[db][0] * inv0, oA[db][1] * inv0);
        *(__half2*)(Op + (size_t)8 * DMODEL + col) =
            __floats2half2_rn(oA[db][2] * inv1, oA[db][3] * inv1);
    }
}

// ---------------------------------------------------------------------------
extern "C" void kernel_launch(void* const* d_in, const int* in_sizes, int n_in,
                              void* d_out, int out_size)
{
    const float* x   = (const float*)d_in[0];
    const float* W_q = (const float*)d_in[1];
    const float* b_q = (const float*)d_in[2];
    const float* W_k = (const float*)d_in[3];
    const float* b_k = (const float*)d_in[4];
    const float* W_v = (const float*)d_in[5];
    const float* b_v = (const float*)d_in[6];
    const float* W_o = (const float*)d_in[7];
    const float* b_o = (const float*)d_in[8];

    float* out = (float*)d_out;
    float* Kc  = out + (size_t)MTOT * DMODEL;
    float* Vc  = Kc  + (size_t)MTOT * DKK;

    __half *xh, *qh, *kh, *vh, *ah;
    cudaGetSymbolAddress((void**)&xh, g_xh);
    cudaGetSymbolAddress((void**)&qh, g_qh);
    cudaGetSymbolAddress((void**)&kh, g_kh);
    cudaGetSymbolAddress((void**)&vh, g_vh);
    cudaGetSymbolAddress((void**)&ah, g_ah);

    cudaFuncSetAttribute(gemm_qkv, cudaFuncAttributeMaxDynamicSharedMemorySize, GEMM_SMEM);
    cudaFuncSetAttribute(gemm_o,   cudaFuncAttributeMaxDynamicSharedMemorySize, GEMM_SMEM);
    cudaFuncSetAttribute(flash_h,  cudaFuncAttributeMaxDynamicSharedMemorySize, FLASH_SMEM);

    const float qscale = 0.08838834764831845f;  // 1/sqrt(128)

    // all fp32->fp16 conversions, one launch
    f2h_all<<<(int)(F2H_TOTAL / 4 / 256), 256>>>(x, W_q, W_k, W_v, W_o);

    // fused Q/K/V projections: grid.x 0-15 Q tiles, 16 K, 17 V
    gemm_qkv<<<dim3(18, MTOT / 128), 256, GEMM_SMEM>>>(
        xh, b_q, b_k, b_v, Kc, Vc, qscale);

    // flash attention -> ah (fp16)
    flash_h<<<dim3(SEQ / 128, NHEADS, BATCH), 256, FLASH_SMEM>>>(qh, kh, vh, ah);

    // output projection -> out (fp32 + bias)
    gemm_o<<<dim3(DMODEL / 128, MTOT / 128), 256, GEMM_SMEM>>>(ah, b_o, out);
}

// round 7
// speedup vs baseline: 8.1677x; 1.0293x over previous
#include <cuda_runtime.h>
#include <cuda_fp16.h>
#include <cstdint>

#define BATCH  2
#define SEQ    2048
#define DMODEL 2048
#define NHEADS 16
#define DKK    128
#define MTOT   (BATCH * SEQ)

#define N_X  ((size_t)MTOT * DMODEL)     // 8388608
#define N_WQ ((size_t)DMODEL * DMODEL)   // 4194304
#define N_WK ((size_t)DMODEL * DKK)      // 262144

// Scratch (allocation-free rule: device globals)
__device__ __half g_xh [N_X];
__device__ __half g_wqh[N_WQ];
__device__ __half g_wkh[N_WK];
__device__ __half g_wvh[N_WK];
__device__ __half g_woh[N_WQ];
__device__ __half g_qh [N_X];            // Q proj, scaled by 1/sqrt(dk)*log2(e), fp16
__device__ __half g_kh [(size_t)MTOT * DKK];
__device__ __half g_vh [(size_t)MTOT * DKK];
__device__ __half g_ah [N_X];            // attention out fp16

// ---------------------------------------------------------------------------
// helpers
// ---------------------------------------------------------------------------
__device__ __forceinline__ uint32_t smem_u32(const void* p) {
    uint32_t a;
    asm("{ .reg .u64 t; cvta.to.shared.u64 t, %1; cvt.u32.u64 %0, t; }" : "=r"(a) : "l"(p));
    return a;
}
#define CP16(dst, src) \
    asm volatile("cp.async.cg.shared.global [%0], [%1], 16;" :: "r"(dst), "l"(src) : "memory")
#define CPCOMMIT() asm volatile("cp.async.commit_group;" ::: "memory")
#define CPWAIT(n)  asm volatile("cp.async.wait_group %0;" :: "n"(n) : "memory")

__device__ __forceinline__ void ldsm4(uint32_t* r, uint32_t a) {
    asm volatile("ldmatrix.sync.aligned.m8n8.x4.shared.b16 {%0,%1,%2,%3}, [%4];"
                 : "=r"(r[0]), "=r"(r[1]), "=r"(r[2]), "=r"(r[3]) : "r"(a));
}
__device__ __forceinline__ void ldsm4t(uint32_t* r, uint32_t a) {
    asm volatile("ldmatrix.sync.aligned.m8n8.x4.trans.shared.b16 {%0,%1,%2,%3}, [%4];"
                 : "=r"(r[0]), "=r"(r[1]), "=r"(r[2]), "=r"(r[3]) : "r"(a));
}
__device__ __forceinline__ void mma16816(float* d, const uint32_t* a, const uint32_t* b) {
    asm volatile(
        "mma.sync.aligned.m16n8k16.row.col.f32.f16.f16.f32 "
        "{%0,%1,%2,%3},{%4,%5,%6,%7},{%8,%9},{%0,%1,%2,%3};"
        : "+f"(d[0]), "+f"(d[1]), "+f"(d[2]), "+f"(d[3])
        : "r"(a[0]), "r"(a[1]), "r"(a[2]), "r"(a[3]), "r"(b[0]), "r"(b[1]));
}
__device__ __forceinline__ void mma16816b(float* d, const uint32_t* a,
                                          uint32_t b0, uint32_t b1) {
    asm volatile(
        "mma.sync.aligned.m16n8k16.row.col.f32.f16.f16.f32 "
        "{%0,%1,%2,%3},{%4,%5,%6,%7},{%8,%9},{%0,%1,%2,%3};"
        : "+f"(d[0]), "+f"(d[1]), "+f"(d[2]), "+f"(d[3])
        : "r"(a[0]), "r"(a[1]), "r"(a[2]), "r"(a[3]), "r"(b0), "r"(b1));
}
__device__ __forceinline__ uint32_t packh2(float lo, float hi) {
    __half2 h = __floats2half2_rn(lo, hi);
    return *(uint32_t*)&h;
}

// ---------------------------------------------------------------------------
// fused fp32 -> fp16: all five tensors in one launch
// ---------------------------------------------------------------------------
#define F2H_TOTAL (N_X + N_WQ + N_WK + N_WK + N_WQ)   // 17301504

__global__ __launch_bounds__(256) void f2h_all(
    const float* __restrict__ x,  const float* __restrict__ wq,
    const float* __restrict__ wk, const float* __restrict__ wv,
    const float* __restrict__ wo)
{
    size_t i = ((size_t)blockIdx.x * 256 + threadIdx.x) * 4;
    const float* s;
    __half* d;
    size_t off;
    if (i < N_X)                            { s = x;  d = g_xh;  off = i; }
    else if (i < N_X + N_WQ)                { s = wq; d = g_wqh; off = i - N_X; }
    else if (i < N_X + N_WQ + N_WK)         { s = wk; d = g_wkh; off = i - N_X - N_WQ; }
    else if (i < N_X + N_WQ + 2 * N_WK)     { s = wv; d = g_wvh; off = i - N_X - N_WQ - N_WK; }
    else                                    { s = wo; d = g_woh; off = i - N_X - N_WQ - 2 * N_WK; }
    float4 v = *(const float4*)(s + off);
    __half2* dp = (__half2*)(d + off);
    dp[0] = __floats2half2_rn(v.x, v.y);
    dp[1] = __floats2half2_rn(v.z, v.w);
}

// ---------------------------------------------------------------------------
// GEMM tile geometry
// ---------------------------------------------------------------------------
#define GS_A 10240            // 128 rows * 80B
#define GS_B 8704             // 32 rows * 272B
#define GS_STAGE (GS_A + GS_B)
#define GEMM_SMEM (3 * GS_STAGE)

// ---------------------------------------------------------------------------
// Fused Q/K/V projection: grid.x 0..15 -> Q col-tiles; 16 -> K; 17 -> V.
// ---------------------------------------------------------------------------
__global__ __launch_bounds__(256, 2) void gemm_qkv(
    const __half* __restrict__ A,
    const float* __restrict__ b_q, const float* __restrict__ b_k,
    const float* __restrict__ b_v,
    float* __restrict__ Kc, float* __restrict__ Vc, float qscale)
{
    extern __shared__ char smc[];
    const uint32_t sb = smem_u32(smc);

    const int tid  = threadIdx.x;
    const int lane = tid & 31;
    const int wid  = tid >> 5;
    const int wm   = wid >> 1;
    const int wn   = wid & 1;
    const int bx   = blockIdx.x;
    const int K    = DMODEL;
    const int NC   = K / 32;
    const int rowBase = blockIdx.y * 128;

    const bool isQ = bx < 16;
    const bool isK = bx == 16;
    const __half* Bsel = isQ ? g_wqh : (isK ? g_wkh : g_wvh);
    const float* biasS = isQ ? b_q : (isK ? b_k : b_v);
    __half* Chf        = isQ ? g_qh : (isK ? g_kh : g_vh);
    float* Cf          = isK ? Kc : Vc;
    const int N        = isQ ? DMODEL : DKK;
    const int colBase  = isQ ? bx * 128 : 0;
    const float hscale = isQ ? qscale : 1.0f;

    auto stage = [&](int c, int s) {
        const int k0 = c * 32;
        const uint32_t sA = sb + s * GS_STAGE;
        const uint32_t sB = sA + GS_A;
#pragma unroll
        for (int i = 0; i < 2; i++) {
            int ch = tid + 256 * i;
            int r = ch >> 2, kc = ch & 3;
            CP16(sA + r * 80 + kc * 16, A + (size_t)(rowBase + r) * K + k0 + kc * 8);
        }
#pragma unroll
        for (int i = 0; i < 2; i++) {
            int ch = tid + 256 * i;
            int r = ch >> 4, nc = ch & 15;
            CP16(sB + r * 272 + nc * 16, Bsel + (size_t)(k0 + r) * N + colBase + nc * 8);
        }
    };

    float acc[2][8][4];
#pragma unroll
    for (int a = 0; a < 2; a++)
#pragma unroll
        for (int b = 0; b < 8; b++)
#pragma unroll
            for (int r = 0; r < 4; r++) acc[a][b][r] = 0.f;

    stage(0, 0); CPCOMMIT();
    stage(1, 1); CPCOMMIT();

    const uint32_t aOff = (wm * 32 + (lane & 15)) * 80 + (lane >> 4) * 16;
    const uint32_t bRow = (lane & 15) * 272;
    const uint32_t bCol = (wn * 64 + 8 * (lane >> 4)) * 2;

    for (int c = 0; c < NC; c++) {
        CPWAIT(1);
        __syncthreads();
        if (c + 2 < NC) stage(c + 2, (c + 2) % 3);
        CPCOMMIT();

        const uint32_t sA = sb + (c % 3) * GS_STAGE;
        const uint32_t sB = sA + GS_A;
#pragma unroll
        for (int ks = 0; ks < 2; ks++) {
            uint32_t a0[4], a1[4];
            ldsm4(a0, sA + aOff + ks * 32);
            ldsm4(a1, sA + aOff + 16 * 80 + ks * 32);
#pragma unroll
            for (int nbp = 0; nbp < 4; nbp++) {
                uint32_t bf[4];
                ldsm4t(bf, sB + bRow + ks * 16 * 272 + bCol + nbp * 32);
                mma16816(acc[0][2 * nbp],     a0, bf);
                mma16816(acc[0][2 * nbp + 1], a0, bf + 2);
                mma16816(acc[1][2 * nbp],     a1, bf);
                mma16816(acc[1][2 * nbp + 1], a1, bf + 2);
            }
        }
    }

    const int g = lane >> 2, q = lane & 3;
#pragma unroll
    for (int mb = 0; mb < 2; mb++) {
        int row = rowBase + wm * 32 + mb * 16 + g;
#pragma unroll
        for (int nb = 0; nb < 8; nb++) {
            int col = colBase + wn * 64 + nb * 8 + 2 * q;
            float b0 = biasS[col], b1 = biasS[col + 1];
            float v0 = acc[mb][nb][0] + b0, v1 = acc[mb][nb][1] + b1;
            float v2 = acc[mb][nb][2] + b0, v3 = acc[mb][nb][3] + b1;
            *(__half2*)(Chf + (size_t)row * N + col) =
                __floats2half2_rn(v0 * hscale, v1 * hscale);
            *(__half2*)(Chf + (size_t)(row + 8) * N + col) =
                __floats2half2_rn(v2 * hscale, v3 * hscale);
            if (!isQ) {
                *(float2*)(Cf + (size_t)row * N + col)       = make_float2(v0, v1);
                *(float2*)(Cf + (size_t)(row + 8) * N + col) = make_float2(v2, v3);
            }
        }
    }
}

// ---------------------------------------------------------------------------
// Output projection GEMM: out(fp32) = ah @ woh + b_o
// ---------------------------------------------------------------------------
__global__ __launch_bounds__(256, 2) void gemm_o(
    const __half* __restrict__ A, const float* __restrict__ bias,
    float* __restrict__ C)
{
    extern __shared__ char smc[];
    const uint32_t sb = smem_u32(smc);

    const int tid  = threadIdx.x;
    const int lane = tid & 31;
    const int wid  = tid >> 5;
    const int wm   = wid >> 1;
    const int wn   = wid & 1;
    const int N = DMODEL, K = DMODEL, NC = K / 32;
    const int rowBase = blockIdx.y * 128;
    const int colBase = blockIdx.x * 128;

    auto stage = [&](int c, int s) {
        const int k0 = c * 32;
        const uint32_t sA = sb + s * GS_STAGE;
        const uint32_t sB = sA + GS_A;
#pragma unroll
        for (int i = 0; i < 2; i++) {
            int ch = tid + 256 * i;
            int r = ch >> 2, kc = ch & 3;
            CP16(sA + r * 80 + kc * 16, A + (size_t)(rowBase + r) * K + k0 + kc * 8);
        }
#pragma unroll
        for (int i = 0; i < 2; i++) {
            int ch = tid + 256 * i;
            int r = ch >> 4, nc = ch & 15;
            CP16(sB + r * 272 + nc * 16, g_woh + (size_t)(k0 + r) * N + colBase + nc * 8);
        }
    };

    float acc[2][8][4];
#pragma unroll
    for (int a = 0; a < 2; a++)
#pragma unroll
        for (int b = 0; b < 8; b++)
#pragma unroll
            for (int r = 0; r < 4; r++) acc[a][b][r] = 0.f;

    stage(0, 0); CPCOMMIT();
    stage(1, 1); CPCOMMIT();

    const uint32_t aOff = (wm * 32 + (lane & 15)) * 80 + (lane >> 4) * 16;
    const uint32_t bRow = (lane & 15) * 272;
    const uint32_t bCol = (wn * 64 + 8 * (lane >> 4)) * 2;

    for (int c = 0; c < NC; c++) {
        CPWAIT(1);
        __syncthreads();
        if (c + 2 < NC) stage(c + 2, (c + 2) % 3);
        CPCOMMIT();

        const uint32_t sA = sb + (c % 3) * GS_STAGE;
        const uint32_t sB = sA + GS_A;
#pragma unroll
        for (int ks = 0; ks < 2; ks++) {
            uint32_t a0[4], a1[4];
            ldsm4(a0, sA + aOff + ks * 32);
            ldsm4(a1, sA + aOff + 16 * 80 + ks * 32);
#pragma unroll
            for (int nbp = 0; nbp < 4; nbp++) {
                uint32_t bf[4];
                ldsm4t(bf, sB + bRow + ks * 16 * 272 + bCol + nbp * 32);
                mma16816(acc[0][2 * nbp],     a0, bf);
                mma16816(acc[0][2 * nbp + 1], a0, bf + 2);
                mma16816(acc[1][2 * nbp],     a1, bf);
                mma16816(acc[1][2 * nbp + 1], a1, bf + 2);
            }
        }
    }

    const int g = lane >> 2, q = lane & 3;
#pragma unroll
    for (int mb = 0; mb < 2; mb++) {
        int row = rowBase + wm * 32 + mb * 16 + g;
#pragma unroll
        for (int nb = 0; nb < 8; nb++) {
            int col = colBase + wn * 64 + nb * 8 + 2 * q;
            float b0 = bias[col], b1 = bias[col + 1];
            *(float2*)(C + (size_t)row * N + col) =
                make_float2(acc[mb][nb][0] + b0, acc[mb][nb][1] + b1);
            *(float2*)(C + (size_t)(row + 8) * N + col) =
                make_float2(acc[mb][nb][2] + b0, acc[mb][nb][3] + b1);
        }
    }
}

// ---------------------------------------------------------------------------
// fp16 flash attention (MQA): CTA = 128 threads (4 warps), BQ=64 q-rows,
// warp = 16 rows. 2-stage cp.async K/V ring -> 87KB smem -> 2 CTAs/SM.
// Q pre-scaled by 1/sqrt(dk)*log2(e); softmax in base-2 (exp2f).
// ---------------------------------------------------------------------------
#define FQ_BYTES 17408                 // 64 rows * 272B
#define FK_BYTES 17408                 // 64 rows * 272B
#define FLASH_SMEM (FQ_BYTES + 4 * FK_BYTES)   // 87040 -> 2 CTAs/SM
#define NT (SEQ / 64)

__global__ __launch_bounds__(128, 2) void flash_h(
    const __half* __restrict__ Qh, const __half* __restrict__ Kh,
    const __half* __restrict__ Vh, __half* __restrict__ Ah)
{
    extern __shared__ char smc[];
    const uint32_t sb = smem_u32(smc);
    const uint32_t sQ = sb;
    const uint32_t sK0 = sb + FQ_BYTES;
    const uint32_t sV0 = sb + FQ_BYTES + 2 * FK_BYTES;

    const int tid  = threadIdx.x;
    const int lane = tid & 31;
    const int wid  = tid >> 5;          // 0..3
    const int h  = blockIdx.y;
    const int b  = blockIdx.z;
    const int q0 = blockIdx.x * 64;
    const size_t kvbase = (size_t)b * SEQ;

    auto stageKV = [&](int t) {
        if (t < NT) {
            const uint32_t kb = sK0 + (t & 1) * FK_BYTES;
            const uint32_t vb = sV0 + (t & 1) * FK_BYTES;
            const size_t rowg = kvbase + (size_t)t * 64;
#pragma unroll
            for (int i = 0; i < 8; i++) {
                int ch = tid + 128 * i;
                int r = ch >> 4, nc = ch & 15;
                CP16(kb + r * 272 + nc * 16, Kh + (rowg + r) * DKK + nc * 8);
            }
#pragma unroll
            for (int i = 0; i < 8; i++) {
                int ch = tid + 128 * i;
                int r = ch >> 4, nc = ch & 15;
                CP16(vb + r * 272 + nc * 16, Vh + (rowg + r) * DKK + nc * 8);
            }
        }
    };

    // prologue: Q + K0,V0 (group 0); K1,V1 (group 1)
#pragma unroll
    for (int i = 0; i < 8; i++) {
        int ch = tid + 128 * i;
        int r = ch >> 4, nc = ch & 15;
        CP16(sQ + r * 272 + nc * 16,
             Qh + (size_t)(b * SEQ + q0 + r) * DMODEL + h * DKK + nc * 8);
    }
    stageKV(0); CPCOMMIT();
    stageKV(1); CPCOMMIT();

    CPWAIT(1);
    __syncthreads();

    uint32_t qf[8][4];
    {
        const uint32_t qB = sQ + (wid * 16 + (lane & 15)) * 272 + (lane >> 4) * 16;
#pragma unroll
        for (int ks = 0; ks < 8; ks++) ldsm4(qf[ks], qB + ks * 32);
    }

    float oA[16][4];
#pragma unroll
    for (int i = 0; i < 16; i++)
#pragma unroll
        for (int r = 0; r < 4; r++) oA[i][r] = 0.f;
    float m0 = -1e30f, m1 = -1e30f, l0 = 0.f, l1 = 0.f;

    const uint32_t kOff = (lane & 15) * 272 + (lane >> 4) * 16;
    const uint32_t vRow = (lane & 15) * 272;
    const uint32_t vCol = (lane >> 4) * 16;

    for (int t = 0; t < NT; t++) {
        const uint32_t kB = sK0 + (t & 1) * FK_BYTES;
        const uint32_t vB = sV0 + (t & 1) * FK_BYTES;

        // S = Q @ K^T  (non-trans K: B-frag pairs {r0,r2},{r1,r3})
        float sC[8][4];
#pragma unroll
        for (int i = 0; i < 8; i++)
#pragma unroll
            for (int r = 0; r < 4; r++) sC[i][r] = 0.f;
#pragma unroll
        for (int ks = 0; ks < 8; ks++) {
#pragma unroll
            for (int nbp = 0; nbp < 4; nbp++) {
                uint32_t bf[4];
                ldsm4(bf, kB + nbp * 16 * 272 + kOff + ks * 32);
                mma16816b(sC[2 * nbp],     qf[ks], bf[0], bf[2]);
                mma16816b(sC[2 * nbp + 1], qf[ks], bf[1], bf[3]);
            }
        }

        // online softmax (base-2 domain; Q pre-scaled by scale*log2e)
        float mx0 = -1e30f, mx1 = -1e30f;
#pragma unroll
        for (int nb = 0; nb < 8; nb++) {
            mx0 = fmaxf(mx0, fmaxf(sC[nb][0], sC[nb][1]));
            mx1 = fmaxf(mx1, fmaxf(sC[nb][2], sC[nb][3]));
        }
        mx0 = fmaxf(mx0, __shfl_xor_sync(0xffffffffu, mx0, 1));
        mx0 = fmaxf(mx0, __shfl_xor_sync(0xffffffffu, mx0, 2));
        mx1 = fmaxf(mx1, __shfl_xor_sync(0xffffffffu, mx1, 1));
        mx1 = fmaxf(mx1, __shfl_xor_sync(0xffffffffu, mx1, 2));
        float mn0 = fmaxf(m0, mx0), mn1 = fmaxf(m1, mx1);
        float cr0 = exp2f(m0 - mn0), cr1 = exp2f(m1 - mn1);
        m0 = mn0; m1 = mn1;
        float rs0 = 0.f, rs1 = 0.f;
#pragma unroll
        for (int nb = 0; nb < 8; nb++) {
            sC[nb][0] = exp2f(sC[nb][0] - mn0);
            sC[nb][1] = exp2f(sC[nb][1] - mn0);
            sC[nb][2] = exp2f(sC[nb][2] - mn1);
            sC[nb][3] = exp2f(sC[nb][3] - mn1);
            rs0 += sC[nb][0] + sC[nb][1];
            rs1 += sC[nb][2] + sC[nb][3];
        }
        rs0 += __shfl_xor_sync(0xffffffffu, rs0, 1);
        rs0 += __shfl_xor_sync(0xffffffffu, rs0, 2);
        rs1 += __shfl_xor_sync(0xffffffffu, rs1, 1);
        rs1 += __shfl_xor_sync(0xffffffffu, rs1, 2);
        l0 = l0 * cr0 + rs0;
        l1 = l1 * cr1 + rs1;
#pragma unroll
        for (int db = 0; db < 16; db++) {
            oA[db][0] *= cr0; oA[db][1] *= cr0;
            oA[db][2] *= cr1; oA[db][3] *= cr1;
        }

        // P: C-frag -> A-frag, in registers (fp16)
        uint32_t pf[4][4];
#pragma unroll
        for (int s = 0; s < 4; s++) {
            pf[s][0] = packh2(sC[2 * s][0],     sC[2 * s][1]);
            pf[s][1] = packh2(sC[2 * s][2],     sC[2 * s][3]);
            pf[s][2] = packh2(sC[2 * s + 1][0], sC[2 * s + 1][1]);
            pf[s][3] = packh2(sC[2 * s + 1][2], sC[2 * s + 1][3]);
        }

        // O += P @ V
#pragma unroll
        for (int s = 0; s < 4; s++) {
#pragma unroll
            for (int dbp = 0; dbp < 8; dbp++) {
                uint32_t vf[4];
                ldsm4t(vf, vB + s * 16 * 272 + vRow + (dbp * 16) * 2 + vCol);
                mma16816(oA[2 * dbp],     pf[s], vf);
                mma16816(oA[2 * dbp + 1], pf[s], vf + 2);
            }
        }

        // done reading buffer t; refill it with t+2, then wait for t+1
        __syncthreads();
        stageKV(t + 2);
        CPCOMMIT();
        CPWAIT(1);
        __syncthreads();
    }

    const float inv0 = 1.f / l0, inv1 = 1.f / l1;
    const int g = lane >> 2, q = lane & 3;
    const int row = q0 + wid * 16 + g;
    __half* Op = Ah + (size_t)(b * SEQ + row) * DMODEL + h * DKK;
#pragma unroll
    for (int db = 0; db < 16; db++) {
        int col = db * 8 + 2 * q;
        *(__half2*)(Op + col) = __floats2half2_rn(oA[db][0] * inv0, oA[db][1] * inv0);
        *(__half2*)(Op + (size_t)8 * DMODEL + col) =
            __floats2half2_rn(oA[db][2] * inv1, oA[db][3] * inv1);
    }
}

// ---------------------------------------------------------------------------
extern "C" void kernel_launch(void* const* d_in, const int* in_sizes, int n_in,
                              void* d_out, int out_size)
{
    const float* x   = (const float*)d_in[0];
    const float* W_q = (const float*)d_in[1];
    const float* b_q = (const float*)d_in[2];
    const float* W_k = (const float*)d_in[3];
    const float* b_k = (const float*)d_in[4];
    const float* W_v = (const float*)d_in[5];
    const float* b_v = (const float*)d_in[6];
    const float* W_o = (const float*)d_in[7];
    const float* b_o = (const float*)d_in[8];

    float* out = (float*)d_out;
    float* Kc  = out + (size_t)MTOT * DMODEL;
    float* Vc  = Kc  + (size_t)MTOT * DKK;

    __half *xh, *qh, *kh, *vh, *ah;
    cudaGetSymbolAddress((void**)&xh, g_xh);
    cudaGetSymbolAddress((void**)&qh, g_qh);
    cudaGetSymbolAddress((void**)&kh, g_kh);
    cudaGetSymbolAddress((void**)&vh, g_vh);
    cudaGetSymbolAddress((void**)&ah, g_ah);

    cudaFuncSetAttribute(gemm_qkv, cudaFuncAttributeMaxDynamicSharedMemorySize, GEMM_SMEM);
    cudaFuncSetAttribute(gemm_o,   cudaFuncAttributeMaxDynamicSharedMemorySize, GEMM_SMEM);
    cudaFuncSetAttribute(flash_h,  cudaFuncAttributeMaxDynamicSharedMemorySize, FLASH_SMEM);

    // 1/sqrt(128) * log2(e): softmax computed with exp2
    const float qscale = 0.08838834764831845f * 1.4426950408889634f;

    f2h_all<<<(int)(F2H_TOTAL / 4 / 256), 256>>>(x, W_q, W_k, W_v, W_o);

    gemm_qkv<<<dim3(18, MTOT / 128), 256, GEMM_SMEM>>>(
        xh, b_q, b_k, b_v, Kc, Vc, qscale);

    flash_h<<<dim3(SEQ / 64, NHEADS, BATCH), 128, FLASH_SMEM>>>(qh, kh, vh, ah);

    gemm_o<<<dim3(DMODEL / 128, MTOT / 128), 256, GEMM_SMEM>>>(ah, b_o, out);
}

// round 8
// speedup vs baseline: 8.2983x; 1.0160x over previous
#include <cuda_runtime.h>
#include <cuda_fp16.h>
#include <cstdint>

#define BATCH  2
#define SEQ    2048
#define DMODEL 2048
#define NHEADS 16
#define DKK    128
#define MTOT   (BATCH * SEQ)

#define N_X  ((size_t)MTOT * DMODEL)     // 8388608
#define N_WQ ((size_t)DMODEL * DMODEL)   // 4194304
#define N_WK ((size_t)DMODEL * DKK)      // 262144

// Scratch (allocation-free rule: device globals)
__device__ __half g_xh [N_X];
__device__ __half g_wqh[N_WQ];
__device__ __half g_wkh[N_WK];
__device__ __half g_wvh[N_WK];
__device__ __half g_woh[N_WQ];
__device__ __half g_qh [N_X];            // Q proj, scaled by 1/sqrt(dk)*log2(e), fp16
__device__ __half g_kh [(size_t)MTOT * DKK];
__device__ __half g_vh [(size_t)MTOT * DKK];
__device__ __half g_ah [N_X];            // attention out fp16

// ---------------------------------------------------------------------------
// helpers
// ---------------------------------------------------------------------------
__device__ __forceinline__ uint32_t smem_u32(const void* p) {
    uint32_t a;
    asm("{ .reg .u64 t; cvta.to.shared.u64 t, %1; cvt.u32.u64 %0, t; }" : "=r"(a) : "l"(p));
    return a;
}
#define CP16(dst, src) \
    asm volatile("cp.async.cg.shared.global [%0], [%1], 16;" :: "r"(dst), "l"(src) : "memory")
#define CPCOMMIT() asm volatile("cp.async.commit_group;" ::: "memory")
#define CPWAIT(n)  asm volatile("cp.async.wait_group %0;" :: "n"(n) : "memory")

__device__ __forceinline__ void ldsm4(uint32_t* r, uint32_t a) {
    asm volatile("ldmatrix.sync.aligned.m8n8.x4.shared.b16 {%0,%1,%2,%3}, [%4];"
                 : "=r"(r[0]), "=r"(r[1]), "=r"(r[2]), "=r"(r[3]) : "r"(a));
}
__device__ __forceinline__ void ldsm4t(uint32_t* r, uint32_t a) {
    asm volatile("ldmatrix.sync.aligned.m8n8.x4.trans.shared.b16 {%0,%1,%2,%3}, [%4];"
                 : "=r"(r[0]), "=r"(r[1]), "=r"(r[2]), "=r"(r[3]) : "r"(a));
}
__device__ __forceinline__ void mma16816(float* d, const uint32_t* a, const uint32_t* b) {
    asm volatile(
        "mma.sync.aligned.m16n8k16.row.col.f32.f16.f16.f32 "
        "{%0,%1,%2,%3},{%4,%5,%6,%7},{%8,%9},{%0,%1,%2,%3};"
        : "+f"(d[0]), "+f"(d[1]), "+f"(d[2]), "+f"(d[3])
        : "r"(a[0]), "r"(a[1]), "r"(a[2]), "r"(a[3]), "r"(b[0]), "r"(b[1]));
}
__device__ __forceinline__ void mma16816b(float* d, const uint32_t* a,
                                          uint32_t b0, uint32_t b1) {
    asm volatile(
        "mma.sync.aligned.m16n8k16.row.col.f32.f16.f16.f32 "
        "{%0,%1,%2,%3},{%4,%5,%6,%7},{%8,%9},{%0,%1,%2,%3};"
        : "+f"(d[0]), "+f"(d[1]), "+f"(d[2]), "+f"(d[3])
        : "r"(a[0]), "r"(a[1]), "r"(a[2]), "r"(a[3]), "r"(b0), "r"(b1));
}
__device__ __forceinline__ uint32_t packh2(float lo, float hi) {
    __half2 h = __floats2half2_rn(lo, hi);
    return *(uint32_t*)&h;
}

// ---------------------------------------------------------------------------
// fused fp32 -> fp16: all five tensors in one launch
// ---------------------------------------------------------------------------
#define F2H_TOTAL (N_X + N_WQ + N_WK + N_WK + N_WQ)   // 17301504

__global__ __launch_bounds__(256) void f2h_all(
    const float* __restrict__ x,  const float* __restrict__ wq,
    const float* __restrict__ wk, const float* __restrict__ wv,
    const float* __restrict__ wo)
{
    size_t i = ((size_t)blockIdx.x * 256 + threadIdx.x) * 4;
    const float* s;
    __half* d;
    size_t off;
    if (i < N_X)                            { s = x;  d = g_xh;  off = i; }
    else if (i < N_X + N_WQ)                { s = wq; d = g_wqh; off = i - N_X; }
    else if (i < N_X + N_WQ + N_WK)         { s = wk; d = g_wkh; off = i - N_X - N_WQ; }
    else if (i < N_X + N_WQ + 2 * N_WK)     { s = wv; d = g_wvh; off = i - N_X - N_WQ - N_WK; }
    else                                    { s = wo; d = g_woh; off = i - N_X - N_WQ - 2 * N_WK; }
    float4 v = *(const float4*)(s + off);
    __half2* dp = (__half2*)(d + off);
    dp[0] = __floats2half2_rn(v.x, v.y);
    dp[1] = __floats2half2_rn(v.z, v.w);
}

// ---------------------------------------------------------------------------
// GEMM tile geometry: BM=128 BN=128 BK=32, 4-stage cp.async pipeline
// ---------------------------------------------------------------------------
#define GS_A 10240            // 128 rows * 80B
#define GS_B 8704             // 32 rows * 272B
#define GS_STAGE (GS_A + GS_B)
#define GEMM_SMEM (4 * GS_STAGE)   // 75776

// ---------------------------------------------------------------------------
// Fused Q/K/V projection: grid.x 0..15 -> Q col-tiles; 16 -> K; 17 -> V.
// ---------------------------------------------------------------------------
__global__ __launch_bounds__(256, 2) void gemm_qkv(
    const __half* __restrict__ A,
    const float* __restrict__ b_q, const float* __restrict__ b_k,
    const float* __restrict__ b_v,
    float* __restrict__ Kc, float* __restrict__ Vc, float qscale)
{
    extern __shared__ char smc[];
    const uint32_t sb = smem_u32(smc);

    const int tid  = threadIdx.x;
    const int lane = tid & 31;
    const int wid  = tid >> 5;
    const int wm   = wid >> 1;
    const int wn   = wid & 1;
    const int bx   = blockIdx.x;
    const int K    = DMODEL;
    const int NC   = K / 32;
    const int rowBase = blockIdx.y * 128;

    const bool isQ = bx < 16;
    const bool isK = bx == 16;
    const __half* Bsel = isQ ? g_wqh : (isK ? g_wkh : g_wvh);
    const float* biasS = isQ ? b_q : (isK ? b_k : b_v);
    __half* Chf        = isQ ? g_qh : (isK ? g_kh : g_vh);
    float* Cf          = isK ? Kc : Vc;
    const int N        = isQ ? DMODEL : DKK;
    const int colBase  = isQ ? bx * 128 : 0;
    const float hscale = isQ ? qscale : 1.0f;

    auto stage = [&](int c, int s) {
        const int k0 = c * 32;
        const uint32_t sA = sb + s * GS_STAGE;
        const uint32_t sB = sA + GS_A;
#pragma unroll
        for (int i = 0; i < 2; i++) {
            int ch = tid + 256 * i;
            int r = ch >> 2, kc = ch & 3;
            CP16(sA + r * 80 + kc * 16, A + (size_t)(rowBase + r) * K + k0 + kc * 8);
        }
#pragma unroll
        for (int i = 0; i < 2; i++) {
            int ch = tid + 256 * i;
            int r = ch >> 4, nc = ch & 15;
            CP16(sB + r * 272 + nc * 16, Bsel + (size_t)(k0 + r) * N + colBase + nc * 8);
        }
    };

    float acc[2][8][4];
#pragma unroll
    for (int a = 0; a < 2; a++)
#pragma unroll
        for (int b = 0; b < 8; b++)
#pragma unroll
            for (int r = 0; r < 4; r++) acc[a][b][r] = 0.f;

    stage(0, 0); CPCOMMIT();
    stage(1, 1); CPCOMMIT();
    stage(2, 2); CPCOMMIT();

    const uint32_t aOff = (wm * 32 + (lane & 15)) * 80 + (lane >> 4) * 16;
    const uint32_t bRow = (lane & 15) * 272;
    const uint32_t bCol = (wn * 64 + 8 * (lane >> 4)) * 2;

    for (int c = 0; c < NC; c++) {
        CPWAIT(2);
        __syncthreads();
        if (c + 3 < NC) stage(c + 3, (c + 3) & 3);
        CPCOMMIT();

        const uint32_t sA = sb + (c & 3) * GS_STAGE;
        const uint32_t sB = sA + GS_A;
#pragma unroll
        for (int ks = 0; ks < 2; ks++) {
            uint32_t a0[4], a1[4];
            ldsm4(a0, sA + aOff + ks * 32);
            ldsm4(a1, sA + aOff + 16 * 80 + ks * 32);
#pragma unroll
            for (int nbp = 0; nbp < 4; nbp++) {
                uint32_t bf[4];
                ldsm4t(bf, sB + bRow + ks * 16 * 272 + bCol + nbp * 32);
                mma16816(acc[0][2 * nbp],     a0, bf);
                mma16816(acc[0][2 * nbp + 1], a0, bf + 2);
                mma16816(acc[1][2 * nbp],     a1, bf);
                mma16816(acc[1][2 * nbp + 1], a1, bf + 2);
            }
        }
    }

    const int g = lane >> 2, q = lane & 3;
#pragma unroll
    for (int mb = 0; mb < 2; mb++) {
        int row = rowBase + wm * 32 + mb * 16 + g;
#pragma unroll
        for (int nb = 0; nb < 8; nb++) {
            int col = colBase + wn * 64 + nb * 8 + 2 * q;
            float b0 = biasS[col], b1 = biasS[col + 1];
            float v0 = acc[mb][nb][0] + b0, v1 = acc[mb][nb][1] + b1;
            float v2 = acc[mb][nb][2] + b0, v3 = acc[mb][nb][3] + b1;
            *(__half2*)(Chf + (size_t)row * N + col) =
                __floats2half2_rn(v0 * hscale, v1 * hscale);
            *(__half2*)(Chf + (size_t)(row + 8) * N + col) =
                __floats2half2_rn(v2 * hscale, v3 * hscale);
            if (!isQ) {
                *(float2*)(Cf + (size_t)row * N + col)       = make_float2(v0, v1);
                *(float2*)(Cf + (size_t)(row + 8) * N + col) = make_float2(v2, v3);
            }
        }
    }
}

// ---------------------------------------------------------------------------
// Output projection GEMM: out(fp32) = ah @ woh + b_o
// ---------------------------------------------------------------------------
__global__ __launch_bounds__(256, 2) void gemm_o(
    const __half* __restrict__ A, const float* __restrict__ bias,
    float* __restrict__ C)
{
    extern __shared__ char smc[];
    const uint32_t sb = smem_u32(smc);

    const int tid  = threadIdx.x;
    const int lane = tid & 31;
    const int wid  = tid >> 5;
    const int wm   = wid >> 1;
    const int wn   = wid & 1;
    const int N = DMODEL, K = DMODEL, NC = K / 32;
    const int rowBase = blockIdx.y * 128;
    const int colBase = blockIdx.x * 128;

    auto stage = [&](int c, int s) {
        const int k0 = c * 32;
        const uint32_t sA = sb + s * GS_STAGE;
        const uint32_t sB = sA + GS_A;
#pragma unroll
        for (int i = 0; i < 2; i++) {
            int ch = tid + 256 * i;
            int r = ch >> 2, kc = ch & 3;
            CP16(sA + r * 80 + kc * 16, A + (size_t)(rowBase + r) * K + k0 + kc * 8);
        }
#pragma unroll
        for (int i = 0; i < 2; i++) {
            int ch = tid + 256 * i;
            int r = ch >> 4, nc = ch & 15;
            CP16(sB + r * 272 + nc * 16, g_woh + (size_t)(k0 + r) * N + colBase + nc * 8);
        }
    };

    float acc[2][8][4];
#pragma unroll
    for (int a = 0; a < 2; a++)
#pragma unroll
        for (int b = 0; b < 8; b++)
#pragma unroll
            for (int r = 0; r < 4; r++) acc[a][b][r] = 0.f;

    stage(0, 0); CPCOMMIT();
    stage(1, 1); CPCOMMIT();
    stage(2, 2); CPCOMMIT();

    const uint32_t aOff = (wm * 32 + (lane & 15)) * 80 + (lane >> 4) * 16;
    const uint32_t bRow = (lane & 15) * 272;
    const uint32_t bCol = (wn * 64 + 8 * (lane >> 4)) * 2;

    for (int c = 0; c < NC; c++) {
        CPWAIT(2);
        __syncthreads();
        if (c + 3 < NC) stage(c + 3, (c + 3) & 3);
        CPCOMMIT();

        const uint32_t sA = sb + (c & 3) * GS_STAGE;
        const uint32_t sB = sA + GS_A;
#pragma unroll
        for (int ks = 0; ks < 2; ks++) {
            uint32_t a0[4], a1[4];
            ldsm4(a0, sA + aOff + ks * 32);
            ldsm4(a1, sA + aOff + 16 * 80 + ks * 32);
#pragma unroll
            for (int nbp = 0; nbp < 4; nbp++) {
                uint32_t bf[4];
                ldsm4t(bf, sB + bRow + ks * 16 * 272 + bCol + nbp * 32);
                mma16816(acc[0][2 * nbp],     a0, bf);
                mma16816(acc[0][2 * nbp + 1], a0, bf + 2);
                mma16816(acc[1][2 * nbp],     a1, bf);
                mma16816(acc[1][2 * nbp + 1], a1, bf + 2);
            }
        }
    }

    const int g = lane >> 2, q = lane & 3;
#pragma unroll
    for (int mb = 0; mb < 2; mb++) {
        int row = rowBase + wm * 32 + mb * 16 + g;
#pragma unroll
        for (int nb = 0; nb < 8; nb++) {
            int col = colBase + wn * 64 + nb * 8 + 2 * q;
            float b0 = bias[col], b1 = bias[col + 1];
            *(float2*)(C + (size_t)row * N + col) =
                make_float2(acc[mb][nb][0] + b0, acc[mb][nb][1] + b1);
            *(float2*)(C + (size_t)(row + 8) * N + col) =
                make_float2(acc[mb][nb][2] + b0, acc[mb][nb][3] + b1);
        }
    }
}

// ---------------------------------------------------------------------------
// fp16 flash attention (MQA): CTA = 128 threads (4 warps), BQ=64 q-rows.
// 3-buffer interleaved K/V item ring (items K0,V0,K1,V1,... buf=item%3)
// -> smem 69.6KB -> 3 CTAs/SM (12 warps). Softmax base-2 (exp2f).
// ---------------------------------------------------------------------------
#define FITEM 17408                    // 64 rows * 272B
#define FQ_BYTES 17408
#define FLASH_SMEM (FQ_BYTES + 3 * FITEM)   // 69632 -> 3 CTAs/SM
#define NT (SEQ / 64)

__global__ __launch_bounds__(128, 3) void flash_h(
    const __half* __restrict__ Qh, const __half* __restrict__ Kh,
    const __half* __restrict__ Vh, __half* __restrict__ Ah)
{
    extern __shared__ char smc[];
    const uint32_t sb = smem_u32(smc);
    const uint32_t sQ = sb;
    const uint32_t sR = sb + FQ_BYTES;   // 3-buffer ring

    const int tid  = threadIdx.x;
    const int lane = tid & 31;
    const int wid  = tid >> 5;          // 0..3
    const int h  = blockIdx.y;
    const int b  = blockIdx.z;
    const int q0 = blockIdx.x * 64;
    const size_t kvbase = (size_t)b * SEQ;

    // stage item j: j even -> K tile j/2, j odd -> V tile j/2; buf j%3
    auto stageItem = [&](int j) {
        if (j < 2 * NT) {
            const uint32_t base = sR + (j % 3) * FITEM;
            const __half* src = (j & 1) ? Vh : Kh;
            const size_t rowg = kvbase + (size_t)(j >> 1) * 64;
#pragma unroll
            for (int i = 0; i < 8; i++) {
                int ch = tid + 128 * i;
                int r = ch >> 4, nc = ch & 15;
                CP16(base + r * 272 + nc * 16, src + (rowg + r) * DKK + nc * 8);
            }
        }
    };

    // prologue: group0 = Q + K0; group1 = V0; group2 = K1
#pragma unroll
    for (int i = 0; i < 8; i++) {
        int ch = tid + 128 * i;
        int r = ch >> 4, nc = ch & 15;
        CP16(sQ + r * 272 + nc * 16,
             Qh + (size_t)(b * SEQ + q0 + r) * DMODEL + h * DKK + nc * 8);
    }
    stageItem(0); CPCOMMIT();
    stageItem(1); CPCOMMIT();
    stageItem(2); CPCOMMIT();

    CPWAIT(2);               // Q + K0 ready
    __syncthreads();

    uint32_t qf[8][4];
    {
        const uint32_t qB = sQ + (wid * 16 + (lane & 15)) * 272 + (lane >> 4) * 16;
#pragma unroll
        for (int ks = 0; ks < 8; ks++) ldsm4(qf[ks], qB + ks * 32);
    }

    float oA[16][4];
#pragma unroll
    for (int i = 0; i < 16; i++)
#pragma unroll
        for (int r = 0; r < 4; r++) oA[i][r] = 0.f;
    float m0 = -1e30f, m1 = -1e30f, l0 = 0.f, l1 = 0.f;

    const uint32_t kOff = (lane & 15) * 272 + (lane >> 4) * 16;
    const uint32_t vRow = (lane & 15) * 272;
    const uint32_t vCol = (lane >> 4) * 16;

    for (int t = 0; t < NT; t++) {
        const uint32_t kB = sR + ((2 * t) % 3) * FITEM;
        const uint32_t vB = sR + ((2 * t + 1) % 3) * FITEM;

        // K_t ready? groups <= 2t done when 2 newest (2t+1, 2t+2) may pend.
        if (t > 0) { CPWAIT(2); __syncthreads(); }

        // S = Q @ K^T  (non-trans K: B-frag pairs {r0,r2},{r1,r3})
        float sC[8][4];
#pragma unroll
        for (int i = 0; i < 8; i++)
#pragma unroll
            for (int r = 0; r < 4; r++) sC[i][r] = 0.f;
#pragma unroll
        for (int ks = 0; ks < 8; ks++) {
#pragma unroll
            for (int nbp = 0; nbp < 4; nbp++) {
                uint32_t bf[4];
                ldsm4(bf, kB + nbp * 16 * 272 + kOff + ks * 32);
                mma16816b(sC[2 * nbp],     qf[ks], bf[0], bf[2]);
                mma16816b(sC[2 * nbp + 1], qf[ks], bf[1], bf[3]);
            }
        }

        // online softmax (base-2 domain; Q pre-scaled by scale*log2e)
        float mx0 = -1e30f, mx1 = -1e30f;
#pragma unroll
        for (int nb = 0; nb < 8; nb++) {
            mx0 = fmaxf(mx0, fmaxf(sC[nb][0], sC[nb][1]));
            mx1 = fmaxf(mx1, fmaxf(sC[nb][2], sC[nb][3]));
        }
        mx0 = fmaxf(mx0, __shfl_xor_sync(0xffffffffu, mx0, 1));
        mx0 = fmaxf(mx0, __shfl_xor_sync(0xffffffffu, mx0, 2));
        mx1 = fmaxf(mx1, __shfl_xor_sync(0xffffffffu, mx1, 1));
        mx1 = fmaxf(mx1, __shfl_xor_sync(0xffffffffu, mx1, 2));
        float mn0 = fmaxf(m0, mx0), mn1 = fmaxf(m1, mx1);
        float cr0 = exp2f(m0 - mn0), cr1 = exp2f(m1 - mn1);
        m0 = mn0; m1 = mn1;
        float rs0 = 0.f, rs1 = 0.f;
#pragma unroll
        for (int nb = 0; nb < 8; nb++) {
            sC[nb][0] = exp2f(sC[nb][0] - mn0);
            sC[nb][1] = exp2f(sC[nb][1] - mn0);
            sC[nb][2] = exp2f(sC[nb][2] - mn1);
            sC[nb][3] = exp2f(sC[nb][3] - mn1);
            rs0 += sC[nb][0] + sC[nb][1];
            rs1 += sC[nb][2] + sC[nb][3];
        }
        rs0 += __shfl_xor_sync(0xffffffffu, rs0, 1);
        rs0 += __shfl_xor_sync(0xffffffffu, rs0, 2);
        rs1 += __shfl_xor_sync(0xffffffffu, rs1, 1);
        rs1 += __shfl_xor_sync(0xffffffffu, rs1, 2);
        l0 = l0 * cr0 + rs0;
        l1 = l1 * cr1 + rs1;
#pragma unroll
        for (int db = 0; db < 16; db++) {
            oA[db][0] *= cr0; oA[db][1] *= cr0;
            oA[db][2] *= cr1; oA[db][3] *= cr1;
        }

        // P: C-frag -> A-frag, in registers (fp16)
        uint32_t pf[4][4];
#pragma unroll
        for (int s = 0; s < 4; s++) {
            pf[s][0] = packh2(sC[2 * s][0],     sC[2 * s][1]);
            pf[s][1] = packh2(sC[2 * s][2],     sC[2 * s][3]);
            pf[s][2] = packh2(sC[2 * s + 1][0], sC[2 * s + 1][1]);
            pf[s][3] = packh2(sC[2 * s + 1][2], sC[2 * s + 1][3]);
        }

        // everyone done reading K_t -> reuse its buffer for V_{t+1}
        __syncthreads();
        stageItem(2 * t + 3);   // V_{t+1} into buf (2t+3)%3 == K_t's buf
        CPCOMMIT();
        CPWAIT(2);              // V_t ready (2t+2, 2t+3 may pend)
        __syncthreads();

        // O += P @ V
#pragma unroll
        for (int s = 0; s < 4; s++) {
#pragma unroll
            for (int dbp = 0; dbp < 8; dbp++) {
                uint32_t vf[4];
                ldsm4t(vf, vB + s * 16 * 272 + vRow + (dbp * 16) * 2 + vCol);
                mma16816(oA[2 * dbp],     pf[s], vf);
                mma16816(oA[2 * dbp + 1], pf[s], vf + 2);
            }
        }

        // everyone done reading V_t -> reuse its buffer for K_{t+2}
        __syncthreads();
        stageItem(2 * t + 4);   // K_{t+2} into buf (2t+4)%3 == V_t's buf
        CPCOMMIT();
    }

    const float inv0 = 1.f / l0, inv1 = 1.f / l1;
    const int g = lane >> 2, q = lane & 3;
    const int row = q0 + wid * 16 + g;
    __half* Op = Ah + (size_t)(b * SEQ + row) * DMODEL + h * DKK;
#pragma unroll
    for (int db = 0; db < 16; db++) {
        int col = db * 8 + 2 * q;
        *(__half2*)(Op + col) = __floats2half2_rn(oA[db][0] * inv0, oA[db][1] * inv0);
        *(__half2*)(Op + (size_t)8 * DMODEL + col) =
            __floats2half2_rn(oA[db][2] * inv1, oA[db][3] * inv1);
    }
}

// ---------------------------------------------------------------------------
extern "C" void kernel_launch(void* const* d_in, const int* in_sizes, int n_in,
                              void* d_out, int out_size)
{
    const float* x   = (const float*)d_in[0];
    const float* W_q = (const float*)d_in[1];
    const float* b_q = (const float*)d_in[2];
    const float* W_k = (const float*)d_in[3];
    const float* b_k = (const float*)d_in[4];
    const float* W_v = (const float*)d_in[5];
    const float* b_v = (const float*)d_in[6];
    const float* W_o = (const float*)d_in[7];
    const float* b_o = (const float*)d_in[8];

    float* out = (float*)d_out;
    float* Kc  = out + (size_t)MTOT * DMODEL;
    float* Vc  = Kc  + (size_t)MTOT * DKK;

    __half *xh, *qh, *kh, *vh, *ah;
    cudaGetSymbolAddress((void**)&xh, g_xh);
    cudaGetSymbolAddress((void**)&qh, g_qh);
    cudaGetSymbolAddress((void**)&kh, g_kh);
    cudaGetSymbolAddress((void**)&vh, g_vh);
    cudaGetSymbolAddress((void**)&ah, g_ah);

    cudaFuncSetAttribute(gemm_qkv, cudaFuncAttributeMaxDynamicSharedMemorySize, GEMM_SMEM);
    cudaFuncSetAttribute(gemm_o,   cudaFuncAttributeMaxDynamicSharedMemorySize, GEMM_SMEM);
    cudaFuncSetAttribute(flash_h,  cudaFuncAttributeMaxDynamicSharedMemorySize, FLASH_SMEM);

    // 1/sqrt(128) * log2(e): softmax computed with exp2
    const float qscale = 0.08838834764831845f * 1.4426950408889634f;

    f2h_all<<<(int)(F2H_TOTAL / 4 / 256), 256>>>(x, W_q, W_k, W_v, W_o);

    gemm_qkv<<<dim3(18, MTOT / 128), 256, GEMM_SMEM>>>(
        xh, b_q, b_k, b_v, Kc, Vc, qscale);

    flash_h<<<dim3(SEQ / 64, NHEADS, BATCH), 128, FLASH_SMEM>>>(qh, kh, vh, ah);

    gemm_o<<<dim3(DMODEL / 128, MTOT / 128), 256, GEMM_SMEM>>>(ah, b_o, out);
}

// round 9
// speedup vs baseline: 8.3113x; 1.0016x over previous
#include <cuda_runtime.h>
#include <cuda_fp16.h>
#include <cstdint>

#define BATCH  2
#define SEQ    2048
#define DMODEL 2048
#define NHEADS 16
#define DKK    128
#define MTOT   (BATCH * SEQ)

#define N_X  ((size_t)MTOT * DMODEL)     // 8388608
#define N_WQ ((size_t)DMODEL * DMODEL)   // 4194304
#define N_WK ((size_t)DMODEL * DKK)      // 262144

// Scratch (allocation-free rule: device globals)
__device__ __half g_xh [N_X];
__device__ __half g_wqh[N_WQ];
__device__ __half g_wkh[N_WK];
__device__ __half g_wvh[N_WK];
__device__ __half g_woh[N_WQ];
__device__ __half g_qh [N_X];            // Q proj, scaled by 1/sqrt(dk)*log2(e), fp16
__device__ __half g_kh [(size_t)MTOT * DKK];
__device__ __half g_vh [(size_t)MTOT * DKK];
__device__ __half g_ah [N_X];            // attention out fp16

// ---------------------------------------------------------------------------
// helpers
// ---------------------------------------------------------------------------
__device__ __forceinline__ uint32_t smem_u32(const void* p) {
    uint32_t a;
    asm("{ .reg .u64 t; cvta.to.shared.u64 t, %1; cvt.u32.u64 %0, t; }" : "=r"(a) : "l"(p));
    return a;
}
#define CP16(dst, src) \
    asm volatile("cp.async.cg.shared.global [%0], [%1], 16;" :: "r"(dst), "l"(src) : "memory")
#define CPCOMMIT() asm volatile("cp.async.commit_group;" ::: "memory")
#define CPWAIT(n)  asm volatile("cp.async.wait_group %0;" :: "n"(n) : "memory")

__device__ __forceinline__ void ldsm4(uint32_t* r, uint32_t a) {
    asm volatile("ldmatrix.sync.aligned.m8n8.x4.shared.b16 {%0,%1,%2,%3}, [%4];"
                 : "=r"(r[0]), "=r"(r[1]), "=r"(r[2]), "=r"(r[3]) : "r"(a));
}
__device__ __forceinline__ void ldsm4t(uint32_t* r, uint32_t a) {
    asm volatile("ldmatrix.sync.aligned.m8n8.x4.trans.shared.b16 {%0,%1,%2,%3}, [%4];"
                 : "=r"(r[0]), "=r"(r[1]), "=r"(r[2]), "=r"(r[3]) : "r"(a));
}
__device__ __forceinline__ void mma16816(float* d, const uint32_t* a, const uint32_t* b) {
    asm volatile(
        "mma.sync.aligned.m16n8k16.row.col.f32.f16.f16.f32 "
        "{%0,%1,%2,%3},{%4,%5,%6,%7},{%8,%9},{%0,%1,%2,%3};"
        : "+f"(d[0]), "+f"(d[1]), "+f"(d[2]), "+f"(d[3])
        : "r"(a[0]), "r"(a[1]), "r"(a[2]), "r"(a[3]), "r"(b[0]), "r"(b[1]));
}
__device__ __forceinline__ void mma16816b(float* d, const uint32_t* a,
                                          uint32_t b0, uint32_t b1) {
    asm volatile(
        "mma.sync.aligned.m16n8k16.row.col.f32.f16.f16.f32 "
        "{%0,%1,%2,%3},{%4,%5,%6,%7},{%8,%9},{%0,%1,%2,%3};"
        : "+f"(d[0]), "+f"(d[1]), "+f"(d[2]), "+f"(d[3])
        : "r"(a[0]), "r"(a[1]), "r"(a[2]), "r"(a[3]), "r"(b0), "r"(b1));
}
__device__ __forceinline__ uint32_t packh2(float lo, float hi) {
    __half2 h = __floats2half2_rn(lo, hi);
    return *(uint32_t*)&h;
}

// ---------------------------------------------------------------------------
// fused fp32 -> fp16: all five tensors in one launch
// ---------------------------------------------------------------------------
#define F2H_TOTAL (N_X + N_WQ + N_WK + N_WK + N_WQ)   // 17301504

__global__ __launch_bounds__(256) void f2h_all(
    const float* __restrict__ x,  const float* __restrict__ wq,
    const float* __restrict__ wk, const float* __restrict__ wv,
    const float* __restrict__ wo)
{
    size_t i = ((size_t)blockIdx.x * 256 + threadIdx.x) * 4;
    const float* s;
    __half* d;
    size_t off;
    if (i < N_X)                            { s = x;  d = g_xh;  off = i; }
    else if (i < N_X + N_WQ)                { s = wq; d = g_wqh; off = i - N_X; }
    else if (i < N_X + N_WQ + N_WK)         { s = wk; d = g_wkh; off = i - N_X - N_WQ; }
    else if (i < N_X + N_WQ + 2 * N_WK)     { s = wv; d = g_wvh; off = i - N_X - N_WQ - N_WK; }
    else                                    { s = wo; d = g_woh; off = i - N_X - N_WQ - 2 * N_WK; }
    float4 v = *(const float4*)(s + off);
    __half2* dp = (__half2*)(d + off);
    dp[0] = __floats2half2_rn(v.x, v.y);
    dp[1] = __floats2half2_rn(v.z, v.w);
}

// ---------------------------------------------------------------------------
// GEMM tile geometry: CTA = 128 thr (4 warps 2x2), BM=64 BN=128 BK=32,
// 4-stage cp.async ring, cross-chunk REGISTER-pipelined fragments:
// while HMMA on chunk c runs, LDSM for chunk c+1 is already in flight.
// __launch_bounds__(128,2): 256-reg budget holds two 48-reg fragment sets.
// ---------------------------------------------------------------------------
#define GS_A 5120             // 64 rows * 80B
#define GS_B 8704             // 32 rows * 272B
#define GS_STAGE (GS_A + GS_B)    // 13824
#define GEMM_SMEM (4 * GS_STAGE)  // 55296

// Shared mainloop body as a macro to keep both kernels identical.
// Expects in scope: sb, tid, lane, wm, wn, NC, acc, and lambdas stage/ldfr/domma.
#define GEMM_MAINLOOP()                                                        \
    stage(0, 0); CPCOMMIT();                                                   \
    stage(1, 1); CPCOMMIT();                                                   \
    stage(2, 2); CPCOMMIT();                                                   \
    CPWAIT(2); __syncthreads();                                                \
    ldfr(0, 0);                                                                \
    for (int c = 0; c < NC; c += 2) {                                          \
        /* even: compute set0, prefetch set1 <- buf c+1 */                     \
        CPWAIT(1); __syncthreads();                                            \
        ldfr(1, (c + 1) & 3);                                                  \
        if (c + 3 < NC) stage(c + 3, (c + 3) & 3);                             \
        CPCOMMIT();                                                            \
        domma(0);                                                              \
        /* odd: compute set1, prefetch set0 <- buf c+2 */                      \
        if (c + 2 < NC) {                                                      \
            CPWAIT(1); __syncthreads();                                        \
            ldfr(0, (c + 2) & 3);                                              \
        }                                                                      \
        if (c + 4 < NC) stage(c + 4, (c + 4) & 3);                             \
        CPCOMMIT();                                                            \
        domma(1);                                                              \
    }

// ---------------------------------------------------------------------------
// Fused Q/K/V projection: grid.x 0..15 -> Q col-tiles; 16 -> K; 17 -> V.
// ---------------------------------------------------------------------------
__global__ __launch_bounds__(128, 2) void gemm_qkv(
    const __half* __restrict__ A,
    const float* __restrict__ b_q, const float* __restrict__ b_k,
    const float* __restrict__ b_v,
    float* __restrict__ Kc, float* __restrict__ Vc, float qscale)
{
    extern __shared__ char smc[];
    const uint32_t sb = smem_u32(smc);

    const int tid  = threadIdx.x;
    const int lane = tid & 31;
    const int wid  = tid >> 5;
    const int wm   = wid & 1;       // 2 m-tiles of 32
    const int wn   = wid >> 1;      // 2 n-tiles of 64
    const int bx   = blockIdx.x;
    const int K    = DMODEL;
    const int NC   = K / 32;
    const int rowBase = blockIdx.y * 64;

    const bool isQ = bx < 16;
    const bool isK = bx == 16;
    const __half* Bsel = isQ ? g_wqh : (isK ? g_wkh : g_wvh);
    const float* biasS = isQ ? b_q : (isK ? b_k : b_v);
    __half* Chf        = isQ ? g_qh : (isK ? g_kh : g_vh);
    float* Cf          = isK ? Kc : Vc;
    const int N        = isQ ? DMODEL : DKK;
    const int colBase  = isQ ? bx * 128 : 0;
    const float hscale = isQ ? qscale : 1.0f;

    auto stage = [&](int c, int s) {
        const int k0 = c * 32;
        const uint32_t sA = sb + s * GS_STAGE;
        const uint32_t sB = sA + GS_A;
#pragma unroll
        for (int i = 0; i < 2; i++) {
            int ch = tid + 128 * i;
            int r = ch >> 2, kc = ch & 3;
            CP16(sA + r * 80 + kc * 16, A + (size_t)(rowBase + r) * K + k0 + kc * 8);
        }
#pragma unroll
        for (int i = 0; i < 4; i++) {
            int ch = tid + 128 * i;
            int r = ch >> 4, nc = ch & 15;
            CP16(sB + r * 272 + nc * 16, Bsel + (size_t)(k0 + r) * N + colBase + nc * 8);
        }
    };

    float acc[2][8][4];
#pragma unroll
    for (int a = 0; a < 2; a++)
#pragma unroll
        for (int b = 0; b < 8; b++)
#pragma unroll
            for (int r = 0; r < 4; r++) acc[a][b][r] = 0.f;

    const uint32_t aOff = (wm * 32 + (lane & 15)) * 80 + (lane >> 4) * 16;
    const uint32_t bRow = (lane & 15) * 272;
    const uint32_t bCol = (wn * 64 + 8 * (lane >> 4)) * 2;

    uint32_t fa[2][2][2][4];   // [set][ks][mt][reg]
    uint32_t fb[2][2][4][4];   // [set][ks][nbp][reg]

    auto ldfr = [&](int set, int bufi) {
        const uint32_t sA = sb + bufi * GS_STAGE;
        const uint32_t sB = sA + GS_A;
#pragma unroll
        for (int ks = 0; ks < 2; ks++) {
            ldsm4(fa[set][ks][0], sA + aOff + ks * 32);
            ldsm4(fa[set][ks][1], sA + aOff + 16 * 80 + ks * 32);
#pragma unroll
            for (int nbp = 0; nbp < 4; nbp++)
                ldsm4t(fb[set][ks][nbp], sB + bRow + ks * 16 * 272 + bCol + nbp * 32);
        }
    };
    auto domma = [&](int set) {
#pragma unroll
        for (int ks = 0; ks < 2; ks++)
#pragma unroll
            for (int nbp = 0; nbp < 4; nbp++) {
                mma16816(acc[0][2 * nbp],     fa[set][ks][0], fb[set][ks][nbp]);
                mma16816(acc[0][2 * nbp + 1], fa[set][ks][0], fb[set][ks][nbp] + 2);
                mma16816(acc[1][2 * nbp],     fa[set][ks][1], fb[set][ks][nbp]);
                mma16816(acc[1][2 * nbp + 1], fa[set][ks][1], fb[set][ks][nbp] + 2);
            }
    };

    GEMM_MAINLOOP();

    const int g = lane >> 2, q = lane & 3;
#pragma unroll
    for (int mb = 0; mb < 2; mb++) {
        int row = rowBase + wm * 32 + mb * 16 + g;
#pragma unroll
        for (int nb = 0; nb < 8; nb++) {
            int col = colBase + wn * 64 + nb * 8 + 2 * q;
            float b0 = biasS[col], b1 = biasS[col + 1];
            float v0 = acc[mb][nb][0] + b0, v1 = acc[mb][nb][1] + b1;
            float v2 = acc[mb][nb][2] + b0, v3 = acc[mb][nb][3] + b1;
            *(__half2*)(Chf + (size_t)row * N + col) =
                __floats2half2_rn(v0 * hscale, v1 * hscale);
            *(__half2*)(Chf + (size_t)(row + 8) * N + col) =
                __floats2half2_rn(v2 * hscale, v3 * hscale);
            if (!isQ) {
                *(float2*)(Cf + (size_t)row * N + col)       = make_float2(v0, v1);
                *(float2*)(Cf + (size_t)(row + 8) * N + col) = make_float2(v2, v3);
            }
        }
    }
}

// ---------------------------------------------------------------------------
// Output projection GEMM: out(fp32) = ah @ woh + b_o
// ---------------------------------------------------------------------------
__global__ __launch_bounds__(128, 2) void gemm_o(
    const __half* __restrict__ A, const float* __restrict__ bias,
    float* __restrict__ C)
{
    extern __shared__ char smc[];
    const uint32_t sb = smem_u32(smc);

    const int tid  = threadIdx.x;
    const int lane = tid & 31;
    const int wid  = tid >> 5;
    const int wm   = wid & 1;
    const int wn   = wid >> 1;
    const int N = DMODEL, K = DMODEL, NC = K / 32;
    const int rowBase = blockIdx.y * 64;
    const int colBase = blockIdx.x * 128;

    auto stage = [&](int c, int s) {
        const int k0 = c * 32;
        const uint32_t sA = sb + s * GS_STAGE;
        const uint32_t sB = sA + GS_A;
#pragma unroll
        for (int i = 0; i < 2; i++) {
            int ch = tid + 128 * i;
            int r = ch >> 2, kc = ch & 3;
            CP16(sA + r * 80 + kc * 16, A + (size_t)(rowBase + r) * K + k0 + kc * 8);
        }
#pragma unroll
        for (int i = 0; i < 4; i++) {
            int ch = tid + 128 * i;
            int r = ch >> 4, nc = ch & 15;
            CP16(sB + r * 272 + nc * 16, g_woh + (size_t)(k0 + r) * N + colBase + nc * 8);
        }
    };

    float acc[2][8][4];
#pragma unroll
    for (int a = 0; a < 2; a++)
#pragma unroll
        for (int b = 0; b < 8; b++)
#pragma unroll
            for (int r = 0; r < 4; r++) acc[a][b][r] = 0.f;

    const uint32_t aOff = (wm * 32 + (lane & 15)) * 80 + (lane >> 4) * 16;
    const uint32_t bRow = (lane & 15) * 272;
    const uint32_t bCol = (wn * 64 + 8 * (lane >> 4)) * 2;

    uint32_t fa[2][2][2][4];
    uint32_t fb[2][2][4][4];

    auto ldfr = [&](int set, int bufi) {
        const uint32_t sA = sb + bufi * GS_STAGE;
        const uint32_t sB = sA + GS_A;
#pragma unroll
        for (int ks = 0; ks < 2; ks++) {
            ldsm4(fa[set][ks][0], sA + aOff + ks * 32);
            ldsm4(fa[set][ks][1], sA + aOff + 16 * 80 + ks * 32);
#pragma unroll
            for (int nbp = 0; nbp < 4; nbp++)
                ldsm4t(fb[set][ks][nbp], sB + bRow + ks * 16 * 272 + bCol + nbp * 32);
        }
    };
    auto domma = [&](int set) {
#pragma unroll
        for (int ks = 0; ks < 2; ks++)
#pragma unroll
            for (int nbp = 0; nbp < 4; nbp++) {
                mma16816(acc[0][2 * nbp],     fa[set][ks][0], fb[set][ks][nbp]);
                mma16816(acc[0][2 * nbp + 1], fa[set][ks][0], fb[set][ks][nbp] + 2);
                mma16816(acc[1][2 * nbp],     fa[set][ks][1], fb[set][ks][nbp]);
                mma16816(acc[1][2 * nbp + 1], fa[set][ks][1], fb[set][ks][nbp] + 2);
            }
    };

    GEMM_MAINLOOP();

    const int g = lane >> 2, q = lane & 3;
#pragma unroll
    for (int mb = 0; mb < 2; mb++) {
        int row = rowBase + wm * 32 + mb * 16 + g;
#pragma unroll
        for (int nb = 0; nb < 8; nb++) {
            int col = colBase + wn * 64 + nb * 8 + 2 * q;
            float b0 = bias[col], b1 = bias[col + 1];
            *(float2*)(C + (size_t)row * N + col) =
                make_float2(acc[mb][nb][0] + b0, acc[mb][nb][1] + b1);
            *(float2*)(C + (size_t)(row + 8) * N + col) =
                make_float2(acc[mb][nb][2] + b0, acc[mb][nb][3] + b1);
        }
    }
}

// ---------------------------------------------------------------------------
// fp16 flash attention (MQA): unchanged from round 8 (passing).
// CTA = 128 thr (4 warps), BQ=64. 3-buffer interleaved K/V item ring.
// ---------------------------------------------------------------------------
#define FITEM 17408                    // 64 rows * 272B
#define FQ_BYTES 17408
#define FLASH_SMEM (FQ_BYTES + 3 * FITEM)   // 69632 -> 3 CTAs/SM
#define NT (SEQ / 64)

__global__ __launch_bounds__(128, 3) void flash_h(
    const __half* __restrict__ Qh, const __half* __restrict__ Kh,
    const __half* __restrict__ Vh, __half* __restrict__ Ah)
{
    extern __shared__ char smc[];
    const uint32_t sb = smem_u32(smc);
    const uint32_t sQ = sb;
    const uint32_t sR = sb + FQ_BYTES;

    const int tid  = threadIdx.x;
    const int lane = tid & 31;
    const int wid  = tid >> 5;
    const int h  = blockIdx.y;
    const int b  = blockIdx.z;
    const int q0 = blockIdx.x * 64;
    const size_t kvbase = (size_t)b * SEQ;

    auto stageItem = [&](int j) {
        if (j < 2 * NT) {
            const uint32_t base = sR + (j % 3) * FITEM;
            const __half* src = (j & 1) ? Vh : Kh;
            const size_t rowg = kvbase + (size_t)(j >> 1) * 64;
#pragma unroll
            for (int i = 0; i < 8; i++) {
                int ch = tid + 128 * i;
                int r = ch >> 4, nc = ch & 15;
                CP16(base + r * 272 + nc * 16, src + (rowg + r) * DKK + nc * 8);
            }
        }
    };

#pragma unroll
    for (int i = 0; i < 8; i++) {
        int ch = tid + 128 * i;
        int r = ch >> 4, nc = ch & 15;
        CP16(sQ + r * 272 + nc * 16,
             Qh + (size_t)(b * SEQ + q0 + r) * DMODEL + h * DKK + nc * 8);
    }
    stageItem(0); CPCOMMIT();
    stageItem(1); CPCOMMIT();
    stageItem(2); CPCOMMIT();

    CPWAIT(2);
    __syncthreads();

    uint32_t qf[8][4];
    {
        const uint32_t qB = sQ + (wid * 16 + (lane & 15)) * 272 + (lane >> 4) * 16;
#pragma unroll
        for (int ks = 0; ks < 8; ks++) ldsm4(qf[ks], qB + ks * 32);
    }

    float oA[16][4];
#pragma unroll
    for (int i = 0; i < 16; i++)
#pragma unroll
        for (int r = 0; r < 4; r++) oA[i][r] = 0.f;
    float m0 = -1e30f, m1 = -1e30f, l0 = 0.f, l1 = 0.f;

    const uint32_t kOff = (lane & 15) * 272 + (lane >> 4) * 16;
    const uint32_t vRow = (lane & 15) * 272;
    const uint32_t vCol = (lane >> 4) * 16;

    for (int t = 0; t < NT; t++) {
        const uint32_t kB = sR + ((2 * t) % 3) * FITEM;
        const uint32_t vB = sR + ((2 * t + 1) % 3) * FITEM;

        if (t > 0) { CPWAIT(2); __syncthreads(); }

        float sC[8][4];
#pragma unroll
        for (int i = 0; i < 8; i++)
#pragma unroll
            for (int r = 0; r < 4; r++) sC[i][r] = 0.f;
#pragma unroll
        for (int ks = 0; ks < 8; ks++) {
#pragma unroll
            for (int nbp = 0; nbp < 4; nbp++) {
                uint32_t bf[4];
                ldsm4(bf, kB + nbp * 16 * 272 + kOff + ks * 32);
                mma16816b(sC[2 * nbp],     qf[ks], bf[0], bf[2]);
                mma16816b(sC[2 * nbp + 1], qf[ks], bf[1], bf[3]);
            }
        }

        float mx0 = -1e30f, mx1 = -1e30f;
#pragma unroll
        for (int nb = 0; nb < 8; nb++) {
            mx0 = fmaxf(mx0, fmaxf(sC[nb][0], sC[nb][1]));
            mx1 = fmaxf(mx1, fmaxf(sC[nb][2], sC[nb][3]));
        }
        mx0 = fmaxf(mx0, __shfl_xor_sync(0xffffffffu, mx0, 1));
        mx0 = fmaxf(mx0, __shfl_xor_sync(0xffffffffu, mx0, 2));
        mx1 = fmaxf(mx1, __shfl_xor_sync(0xffffffffu, mx1, 1));
        mx1 = fmaxf(mx1, __shfl_xor_sync(0xffffffffu, mx1, 2));
        float mn0 = fmaxf(m0, mx0), mn1 = fmaxf(m1, mx1);
        float cr0 = exp2f(m0 - mn0), cr1 = exp2f(m1 - mn1);
        m0 = mn0; m1 = mn1;
        float rs0 = 0.f, rs1 = 0.f;
#pragma unroll
        for (int nb = 0; nb < 8; nb++) {
            sC[nb][0] = exp2f(sC[nb][0] - mn0);
            sC[nb][1] = exp2f(sC[nb][1] - mn0);
            sC[nb][2] = exp2f(sC[nb][2] - mn1);
            sC[nb][3] = exp2f(sC[nb][3] - mn1);
            rs0 += sC[nb][0] + sC[nb][1];
            rs1 += sC[nb][2] + sC[nb][3];
        }
        rs0 += __shfl_xor_sync(0xffffffffu, rs0, 1);
        rs0 += __shfl_xor_sync(0xffffffffu, rs0, 2);
        rs1 += __shfl_xor_sync(0xffffffffu, rs1, 1);
        rs1 += __shfl_xor_sync(0xffffffffu, rs1, 2);
        l0 = l0 * cr0 + rs0;
        l1 = l1 * cr1 + rs1;
#pragma unroll
        for (int db = 0; db < 16; db++) {
            oA[db][0] *= cr0; oA[db][1] *= cr0;
            oA[db][2] *= cr1; oA[db][3] *= cr1;
        }

        uint32_t pf[4][4];
#pragma unroll
        for (int s = 0; s < 4; s++) {
            pf[s][0] = packh2(sC[2 * s][0],     sC[2 * s][1]);
            pf[s][1] = packh2(sC[2 * s][2],     sC[2 * s][3]);
            pf[s][2] = packh2(sC[2 * s + 1][0], sC[2 * s + 1][1]);
            pf[s][3] = packh2(sC[2 * s + 1][2], sC[2 * s + 1][3]);
        }

        __syncthreads();
        stageItem(2 * t + 3);
        CPCOMMIT();
        CPWAIT(2);
        __syncthreads();

#pragma unroll
        for (int s = 0; s < 4; s++) {
#pragma unroll
            for (int dbp = 0; dbp < 8; dbp++) {
                uint32_t vf[4];
                ldsm4t(vf, vB + s * 16 * 272 + vRow + (dbp * 16) * 2 + vCol);
                mma16816(oA[2 * dbp],     pf[s], vf);
                mma16816(oA[2 * dbp + 1], pf[s], vf + 2);
            }
        }

        __syncthreads();
        stageItem(2 * t + 4);
        CPCOMMIT();
    }

    const float inv0 = 1.f / l0, inv1 = 1.f / l1;
    const int g = lane >> 2, q = lane & 3;
    const int row = q0 + wid * 16 + g;
    __half* Op = Ah + (size_t)(b * SEQ + row) * DMODEL + h * DKK;
#pragma unroll
    for (int db = 0; db < 16; db++) {
        int col = db * 8 + 2 * q;
        *(__half2*)(Op + col) = __floats2half2_rn(oA[db][0] * inv0, oA[db][1] * inv0);
        *(__half2*)(Op + (size_t)8 * DMODEL + col) =
            __floats2half2_rn(oA[db][2] * inv1, oA[db][3] * inv1);
    }
}

// ---------------------------------------------------------------------------
extern "C" void kernel_launch(void* const* d_in, const int* in_sizes, int n_in,
                              void* d_out, int out_size)
{
    const float* x   = (const float*)d_in[0];
    const float* W_q = (const float*)d_in[1];
    const float* b_q = (const float*)d_in[2];
    const float* W_k = (const float*)d_in[3];
    const float* b_k = (const float*)d_in[4];
    const float* W_v = (const float*)d_in[5];
    const float* b_v = (const float*)d_in[6];
    const float* W_o = (const float*)d_in[7];
    const float* b_o = (const float*)d_in[8];

    float* out = (float*)d_out;
    float* Kc  = out + (size_t)MTOT * DMODEL;
    float* Vc  = Kc  + (size_t)MTOT * DKK;

    __half *xh, *qh, *kh, *vh, *ah;
    cudaGetSymbolAddress((void**)&xh, g_xh);
    cudaGetSymbolAddress((void**)&qh, g_qh);
    cudaGetSymbolAddress((void**)&kh, g_kh);
    cudaGetSymbolAddress((void**)&vh, g_vh);
    cudaGetSymbolAddress((void**)&ah, g_ah);

    cudaFuncSetAttribute(gemm_qkv, cudaFuncAttributeMaxDynamicSharedMemorySize, GEMM_SMEM);
    cudaFuncSetAttribute(gemm_o,   cudaFuncAttributeMaxDynamicSharedMemorySize, GEMM_SMEM);
    cudaFuncSetAttribute(flash_h,  cudaFuncAttributeMaxDynamicSharedMemorySize, FLASH_SMEM);

    // 1/sqrt(128) * log2(e): softmax computed with exp2
    const float qscale = 0.08838834764831845f * 1.4426950408889634f;

    f2h_all<<<(int)(F2H_TOTAL / 4 / 256), 256>>>(x, W_q, W_k, W_v, W_o);

    gemm_qkv<<<dim3(18, MTOT / 64), 128, GEMM_SMEM>>>(
        xh, b_q, b_k, b_v, Kc, Vc, qscale);

    flash_h<<<dim3(SEQ / 64, NHEADS, BATCH), 128, FLASH_SMEM>>>(qh, kh, vh, ah);

    gemm_o<<<dim3(DMODEL / 128, MTOT / 64), 128, GEMM_SMEM>>>(ah, b_o, out);
}

// round 10
// speedup vs baseline: 8.3287x; 1.0021x over previous
#include <cuda_runtime.h>
#include <cuda_fp16.h>
#include <cstdint>

#define BATCH  2
#define SEQ    2048
#define DMODEL 2048
#define NHEADS 16
#define DKK    128
#define MTOT   (BATCH * SEQ)

#define N_X  ((size_t)MTOT * DMODEL)     // 8388608
#define N_WQ ((size_t)DMODEL * DMODEL)   // 4194304
#define N_WK ((size_t)DMODEL * DKK)      // 262144

// Scratch (allocation-free rule: device globals)
__device__ __half g_xh [N_X];
__device__ __half g_wqh[N_WQ];
__device__ __half g_wkh[N_WK];
__device__ __half g_wvh[N_WK];
__device__ __half g_woh[N_WQ];
__device__ __half g_kh [(size_t)MTOT * DKK];
__device__ __half g_vh [(size_t)MTOT * DKK];
__device__ __half g_ah [N_X];            // attention out fp16

// ---------------------------------------------------------------------------
// helpers
// ---------------------------------------------------------------------------
__device__ __forceinline__ uint32_t smem_u32(const void* p) {
    uint32_t a;
    asm("{ .reg .u64 t; cvta.to.shared.u64 t, %1; cvt.u32.u64 %0, t; }" : "=r"(a) : "l"(p));
    return a;
}
#define CP16(dst, src) \
    asm volatile("cp.async.cg.shared.global [%0], [%1], 16;" :: "r"(dst), "l"(src) : "memory")
#define CPCOMMIT() asm volatile("cp.async.commit_group;" ::: "memory")
#define CPWAIT(n)  asm volatile("cp.async.wait_group %0;" :: "n"(n) : "memory")

__device__ __forceinline__ void ldsm4(uint32_t* r, uint32_t a) {
    asm volatile("ldmatrix.sync.aligned.m8n8.x4.shared.b16 {%0,%1,%2,%3}, [%4];"
                 : "=r"(r[0]), "=r"(r[1]), "=r"(r[2]), "=r"(r[3]) : "r"(a));
}
__device__ __forceinline__ void ldsm4t(uint32_t* r, uint32_t a) {
    asm volatile("ldmatrix.sync.aligned.m8n8.x4.trans.shared.b16 {%0,%1,%2,%3}, [%4];"
                 : "=r"(r[0]), "=r"(r[1]), "=r"(r[2]), "=r"(r[3]) : "r"(a));
}
__device__ __forceinline__ void mma16816(float* d, const uint32_t* a, const uint32_t* b) {
    asm volatile(
        "mma.sync.aligned.m16n8k16.row.col.f32.f16.f16.f32 "
        "{%0,%1,%2,%3},{%4,%5,%6,%7},{%8,%9},{%0,%1,%2,%3};"
        : "+f"(d[0]), "+f"(d[1]), "+f"(d[2]), "+f"(d[3])
        : "r"(a[0]), "r"(a[1]), "r"(a[2]), "r"(a[3]), "r"(b[0]), "r"(b[1]));
}
__device__ __forceinline__ void mma16816b(float* d, const uint32_t* a,
                                          uint32_t b0, uint32_t b1) {
    asm volatile(
        "mma.sync.aligned.m16n8k16.row.col.f32.f16.f16.f32 "
        "{%0,%1,%2,%3},{%4,%5,%6,%7},{%8,%9},{%0,%1,%2,%3};"
        : "+f"(d[0]), "+f"(d[1]), "+f"(d[2]), "+f"(d[3])
        : "r"(a[0]), "r"(a[1]), "r"(a[2]), "r"(a[3]), "r"(b0), "r"(b1));
}
__device__ __forceinline__ uint32_t packh2(float lo, float hi) {
    __half2 h = __floats2half2_rn(lo, hi);
    return *(uint32_t*)&h;
}

// ---------------------------------------------------------------------------
// fused fp32 -> fp16: all five tensors in one launch
// ---------------------------------------------------------------------------
#define F2H_TOTAL (N_X + N_WQ + N_WK + N_WK + N_WQ)   // 17301504

__global__ __launch_bounds__(256) void f2h_all(
    const float* __restrict__ x,  const float* __restrict__ wq,
    const float* __restrict__ wk, const float* __restrict__ wv,
    const float* __restrict__ wo)
{
    size_t i = ((size_t)blockIdx.x * 256 + threadIdx.x) * 4;
    const float* s;
    __half* d;
    size_t off;
    if (i < N_X)                            { s = x;  d = g_xh;  off = i; }
    else if (i < N_X + N_WQ)                { s = wq; d = g_wqh; off = i - N_X; }
    else if (i < N_X + N_WQ + N_WK)         { s = wk; d = g_wkh; off = i - N_X - N_WQ; }
    else if (i < N_X + N_WQ + 2 * N_WK)     { s = wv; d = g_wvh; off = i - N_X - N_WQ - N_WK; }
    else                                    { s = wo; d = g_woh; off = i - N_X - N_WQ - 2 * N_WK; }
    float4 v = *(const float4*)(s + off);
    __half2* dp = (__half2*)(d + off);
    dp[0] = __floats2half2_rn(v.x, v.y);
    dp[1] = __floats2half2_rn(v.z, v.w);
}

// ---------------------------------------------------------------------------
// GEMM tile geometry: CTA = 128 thr (4 warps 2x2), BM=64 BN=128 BK=32,
// 4-stage cp.async ring, cross-chunk register-pipelined fragments.
// ---------------------------------------------------------------------------
#define GS_A 5120             // 64 rows * 80B
#define GS_B 8704             // 32 rows * 272B
#define GS_STAGE (GS_A + GS_B)    // 13824
#define GEMM_SMEM (4 * GS_STAGE)  // 55296

#define GEMM_MAINLOOP()                                                        \
    stage(0, 0); CPCOMMIT();                                                   \
    stage(1, 1); CPCOMMIT();                                                   \
    stage(2, 2); CPCOMMIT();                                                   \
    CPWAIT(2); __syncthreads();                                                \
    ldfr(0, 0);                                                                \
    for (int c = 0; c < NC; c += 2) {                                          \
        CPWAIT(1); __syncthreads();                                            \
        ldfr(1, (c + 1) & 3);                                                  \
        if (c + 3 < NC) stage(c + 3, (c + 3) & 3);                             \
        CPCOMMIT();                                                            \
        domma(0);                                                              \
        if (c + 2 < NC) {                                                      \
            CPWAIT(1); __syncthreads();                                        \
            ldfr(0, (c + 2) & 3);                                              \
        }                                                                      \
        if (c + 4 < NC) stage(c + 4, (c + 4) & 3);                             \
        CPCOMMIT();                                                            \
        domma(1);                                                              \
    }

// ---------------------------------------------------------------------------
// K/V projection (Q is fused into flash): grid.x 0 -> K; 1 -> V.
// ---------------------------------------------------------------------------
__global__ __launch_bounds__(128, 2) void gemm_kv(
    const __half* __restrict__ A,
    const float* __restrict__ b_k, const float* __restrict__ b_v,
    float* __restrict__ Kc, float* __restrict__ Vc)
{
    extern __shared__ char smc[];
    const uint32_t sb = smem_u32(smc);

    const int tid  = threadIdx.x;
    const int lane = tid & 31;
    const int wid  = tid >> 5;
    const int wm   = wid & 1;
    const int wn   = wid >> 1;
    const int K    = DMODEL;
    const int NC   = K / 32;
    const int rowBase = blockIdx.y * 64;

    const bool isK = blockIdx.x == 0;
    const __half* Bsel = isK ? g_wkh : g_wvh;
    const float* biasS = isK ? b_k : b_v;
    __half* Chf        = isK ? g_kh : g_vh;
    float* Cf          = isK ? Kc : Vc;
    const int N        = DKK;

    auto stage = [&](int c, int s) {
        const int k0 = c * 32;
        const uint32_t sA = sb + s * GS_STAGE;
        const uint32_t sB = sA + GS_A;
#pragma unroll
        for (int i = 0; i < 2; i++) {
            int ch = tid + 128 * i;
            int r = ch >> 2, kc = ch & 3;
            CP16(sA + r * 80 + kc * 16, A + (size_t)(rowBase + r) * K + k0 + kc * 8);
        }
#pragma unroll
        for (int i = 0; i < 4; i++) {
            int ch = tid + 128 * i;
            int r = ch >> 4, nc = ch & 15;
            CP16(sB + r * 272 + nc * 16, Bsel + (size_t)(k0 + r) * N + nc * 8);
        }
    };

    float acc[2][8][4];
#pragma unroll
    for (int a = 0; a < 2; a++)
#pragma unroll
        for (int b = 0; b < 8; b++)
#pragma unroll
            for (int r = 0; r < 4; r++) acc[a][b][r] = 0.f;

    const uint32_t aOff = (wm * 32 + (lane & 15)) * 80 + (lane >> 4) * 16;
    const uint32_t bRow = (lane & 15) * 272;
    const uint32_t bCol = (wn * 64 + 8 * (lane >> 4)) * 2;

    uint32_t fa[2][2][2][4];
    uint32_t fb[2][2][4][4];

    auto ldfr = [&](int set, int bufi) {
        const uint32_t sA = sb + bufi * GS_STAGE;
        const uint32_t sB = sA + GS_A;
#pragma unroll
        for (int ks = 0; ks < 2; ks++) {
            ldsm4(fa[set][ks][0], sA + aOff + ks * 32);
            ldsm4(fa[set][ks][1], sA + aOff + 16 * 80 + ks * 32);
#pragma unroll
            for (int nbp = 0; nbp < 4; nbp++)
                ldsm4t(fb[set][ks][nbp], sB + bRow + ks * 16 * 272 + bCol + nbp * 32);
        }
    };
    auto domma = [&](int set) {
#pragma unroll
        for (int ks = 0; ks < 2; ks++)
#pragma unroll
            for (int nbp = 0; nbp < 4; nbp++) {
                mma16816(acc[0][2 * nbp],     fa[set][ks][0], fb[set][ks][nbp]);
                mma16816(acc[0][2 * nbp + 1], fa[set][ks][0], fb[set][ks][nbp] + 2);
                mma16816(acc[1][2 * nbp],     fa[set][ks][1], fb[set][ks][nbp]);
                mma16816(acc[1][2 * nbp + 1], fa[set][ks][1], fb[set][ks][nbp] + 2);
            }
    };

    GEMM_MAINLOOP();

    const int g = lane >> 2, q = lane & 3;
#pragma unroll
    for (int mb = 0; mb < 2; mb++) {
        int row = rowBase + wm * 32 + mb * 16 + g;
#pragma unroll
        for (int nb = 0; nb < 8; nb++) {
            int col = wn * 64 + nb * 8 + 2 * q;
            float b0 = biasS[col], b1 = biasS[col + 1];
            float v0 = acc[mb][nb][0] + b0, v1 = acc[mb][nb][1] + b1;
            float v2 = acc[mb][nb][2] + b0, v3 = acc[mb][nb][3] + b1;
            *(__half2*)(Chf + (size_t)row * N + col) = __floats2half2_rn(v0, v1);
            *(__half2*)(Chf + (size_t)(row + 8) * N + col) = __floats2half2_rn(v2, v3);
            *(float2*)(Cf + (size_t)row * N + col)       = make_float2(v0, v1);
            *(float2*)(Cf + (size_t)(row + 8) * N + col) = make_float2(v2, v3);
        }
    }
}

// ---------------------------------------------------------------------------
// Output projection GEMM: out(fp32) = ah @ woh + b_o
// ---------------------------------------------------------------------------
__global__ __launch_bounds__(128, 2) void gemm_o(
    const __half* __restrict__ A, const float* __restrict__ bias,
    float* __restrict__ C)
{
    extern __shared__ char smc[];
    const uint32_t sb = smem_u32(smc);

    const int tid  = threadIdx.x;
    const int lane = tid & 31;
    const int wid  = tid >> 5;
    const int wm   = wid & 1;
    const int wn   = wid >> 1;
    const int N = DMODEL, K = DMODEL, NC = K / 32;
    const int rowBase = blockIdx.y * 64;
    const int colBase = blockIdx.x * 128;

    auto stage = [&](int c, int s) {
        const int k0 = c * 32;
        const uint32_t sA = sb + s * GS_STAGE;
        const uint32_t sB = sA + GS_A;
#pragma unroll
        for (int i = 0; i < 2; i++) {
            int ch = tid + 128 * i;
            int r = ch >> 2, kc = ch & 3;
            CP16(sA + r * 80 + kc * 16, A + (size_t)(rowBase + r) * K + k0 + kc * 8);
        }
#pragma unroll
        for (int i = 0; i < 4; i++) {
            int ch = tid + 128 * i;
            int r = ch >> 4, nc = ch & 15;
            CP16(sB + r * 272 + nc * 16, g_woh + (size_t)(k0 + r) * N + colBase + nc * 8);
        }
    };

    float acc[2][8][4];
#pragma unroll
    for (int a = 0; a < 2; a++)
#pragma unroll
        for (int b = 0; b < 8; b++)
#pragma unroll
            for (int r = 0; r < 4; r++) acc[a][b][r] = 0.f;

    const uint32_t aOff = (wm * 32 + (lane & 15)) * 80 + (lane >> 4) * 16;
    const uint32_t bRow = (lane & 15) * 272;
    const uint32_t bCol = (wn * 64 + 8 * (lane >> 4)) * 2;

    uint32_t fa[2][2][2][4];
    uint32_t fb[2][2][4][4];

    auto ldfr = [&](int set, int bufi) {
        const uint32_t sA = sb + bufi * GS_STAGE;
        const uint32_t sB = sA + GS_A;
#pragma unroll
        for (int ks = 0; ks < 2; ks++) {
            ldsm4(fa[set][ks][0], sA + aOff + ks * 32);
            ldsm4(fa[set][ks][1], sA + aOff + 16 * 80 + ks * 32);
#pragma unroll
            for (int nbp = 0; nbp < 4; nbp++)
                ldsm4t(fb[set][ks][nbp], sB + bRow + ks * 16 * 272 + bCol + nbp * 32);
        }
    };
    auto domma = [&](int set) {
#pragma unroll
        for (int ks = 0; ks < 2; ks++)
#pragma unroll
            for (int nbp = 0; nbp < 4; nbp++) {
                mma16816(acc[0][2 * nbp],     fa[set][ks][0], fb[set][ks][nbp]);
                mma16816(acc[0][2 * nbp + 1], fa[set][ks][0], fb[set][ks][nbp] + 2);
                mma16816(acc[1][2 * nbp],     fa[set][ks][1], fb[set][ks][nbp]);
                mma16816(acc[1][2 * nbp + 1], fa[set][ks][1], fb[set][ks][nbp] + 2);
            }
    };

    GEMM_MAINLOOP();

    const int g = lane >> 2, q = lane & 3;
#pragma unroll
    for (int mb = 0; mb < 2; mb++) {
        int row = rowBase + wm * 32 + mb * 16 + g;
#pragma unroll
        for (int nb = 0; nb < 8; nb++) {
            int col = colBase + wn * 64 + nb * 8 + 2 * q;
            float b0 = bias[col], b1 = bias[col + 1];
            *(float2*)(C + (size_t)row * N + col) =
                make_float2(acc[mb][nb][0] + b0, acc[mb][nb][1] + b1);
            *(float2*)(C + (size_t)(row + 8) * N + col) =
                make_float2(acc[mb][nb][2] + b0, acc[mb][nb][3] + b1);
        }
    }
}

// ---------------------------------------------------------------------------
// fp16 flash attention (MQA) with FUSED Q-PROJECTION.
// CTA = 128 thr (4 warps), BQ=64. Prologue computes Q tile = x @ Wq[:,h]
// (+bias, *scale) straight into sQ smem via the same mma pipeline, reusing
// the KV ring buffers for staging. Then the standard 3-buffer K/V loop.
// ---------------------------------------------------------------------------
#define FITEM 17408                    // 64 rows * 272B
#define FQ_BYTES 17408
#define FLASH_SMEM (FQ_BYTES + 3 * FITEM)   // 69632 -> 3 CTAs/SM
#define NT (SEQ / 64)
#define QP_A 5120                      // x-chunk bytes within a ring buffer

__global__ __launch_bounds__(128, 3) void flash_h(
    const __half* __restrict__ Xh, const float* __restrict__ b_q,
    const __half* __restrict__ Kh, const __half* __restrict__ Vh,
    __half* __restrict__ Ah, float qscale)
{
    extern __shared__ char smc[];
    const uint32_t sb = smem_u32(smc);
    const uint32_t sQ = sb;
    const uint32_t sR = sb + FQ_BYTES;

    const int tid  = threadIdx.x;
    const int lane = tid & 31;
    const int wid  = tid >> 5;
    const int h  = blockIdx.y;
    const int b  = blockIdx.z;
    const int q0 = blockIdx.x * 64;
    const size_t kvbase = (size_t)b * SEQ;

    // ======================= fused Q projection ==========================
    {
        const int wm = wid & 1, wn = wid >> 1;
        const __half* Ax = Xh + (size_t)(b * SEQ + q0) * DMODEL;

        auto stageQ = [&](int c, int s) {
            const int k0 = c * 32;
            const uint32_t sA = sR + s * FITEM;
            const uint32_t sB = sA + QP_A;
#pragma unroll
            for (int i = 0; i < 2; i++) {
                int ch = tid + 128 * i;
                int r = ch >> 2, kc = ch & 3;
                CP16(sA + r * 80 + kc * 16, Ax + (size_t)r * DMODEL + k0 + kc * 8);
            }
#pragma unroll
            for (int i = 0; i < 4; i++) {
                int ch = tid + 128 * i;
                int r = ch >> 4, nc = ch & 15;
                CP16(sB + r * 272 + nc * 16,
                     g_wqh + (size_t)(k0 + r) * DMODEL + h * DKK + nc * 8);
            }
        };

        float acc[2][8][4];
#pragma unroll
        for (int a = 0; a < 2; a++)
#pragma unroll
            for (int bb = 0; bb < 8; bb++)
#pragma unroll
                for (int r = 0; r < 4; r++) acc[a][bb][r] = 0.f;

        const uint32_t aOff = (wm * 32 + (lane & 15)) * 80 + (lane >> 4) * 16;
        const uint32_t bRow = (lane & 15) * 272;
        const uint32_t bCol = (wn * 64 + 8 * (lane >> 4)) * 2;

        stageQ(0, 0); CPCOMMIT();
        stageQ(1, 1); CPCOMMIT();

        for (int c = 0; c < DMODEL / 32; c++) {
            CPWAIT(1);
            __syncthreads();
            const uint32_t sA = sR + (c & 1) * FITEM;
            const uint32_t sB = sA + QP_A;
#pragma unroll
            for (int ks = 0; ks < 2; ks++) {
                uint32_t a0[4], a1[4];
                ldsm4(a0, sA + aOff + ks * 32);
                ldsm4(a1, sA + aOff + 16 * 80 + ks * 32);
#pragma unroll
                for (int nbp = 0; nbp < 4; nbp++) {
                    uint32_t bf[4];
                    ldsm4t(bf, sB + bRow + ks * 16 * 272 + bCol + nbp * 32);
                    mma16816(acc[0][2 * nbp],     a0, bf);
                    mma16816(acc[0][2 * nbp + 1], a0, bf + 2);
                    mma16816(acc[1][2 * nbp],     a1, bf);
                    mma16816(acc[1][2 * nbp + 1], a1, bf + 2);
                }
            }
            __syncthreads();
            if (c + 2 < DMODEL / 32) stageQ(c + 2, c & 1);
            CPCOMMIT();
        }
        CPWAIT(0);

        // epilogue: bias + scale -> sQ (fp16, canonical row-major 272B rows)
        const int g = lane >> 2, q = lane & 3;
#pragma unroll
        for (int mb = 0; mb < 2; mb++) {
            int row = wm * 32 + mb * 16 + g;
#pragma unroll
            for (int nb = 0; nb < 8; nb++) {
                int col = wn * 64 + nb * 8 + 2 * q;
                float bq0 = b_q[h * DKK + col], bq1 = b_q[h * DKK + col + 1];
                *(__half2*)(smc + row * 272 + col * 2) =
                    __floats2half2_rn((acc[mb][nb][0] + bq0) * qscale,
                                      (acc[mb][nb][1] + bq1) * qscale);
                *(__half2*)(smc + (row + 8) * 272 + col * 2) =
                    __floats2half2_rn((acc[mb][nb][2] + bq0) * qscale,
                                      (acc[mb][nb][3] + bq1) * qscale);
            }
        }
        __syncthreads();
    }

    // ======================= K/V attention loop ==========================
    auto stageItem = [&](int j) {
        if (j < 2 * NT) {
            const uint32_t base = sR + (j % 3) * FITEM;
            const __half* src = (j & 1) ? Vh : Kh;
            const size_t rowg = kvbase + (size_t)(j >> 1) * 64;
#pragma unroll
            for (int i = 0; i < 8; i++) {
                int ch = tid + 128 * i;
                int r = ch >> 4, nc = ch & 15;
                CP16(base + r * 272 + nc * 16, src + (rowg + r) * DKK + nc * 8);
            }
        }
    };

    stageItem(0); CPCOMMIT();
    stageItem(1); CPCOMMIT();
    stageItem(2); CPCOMMIT();

    // load persistent Q fragments from sQ (written by the fused projection)
    uint32_t qf[8][4];
    {
        const uint32_t qB = sQ + (wid * 16 + (lane & 15)) * 272 + (lane >> 4) * 16;
#pragma unroll
        for (int ks = 0; ks < 8; ks++) ldsm4(qf[ks], qB + ks * 32);
    }

    CPWAIT(2);       // K0 ready
    __syncthreads();

    float oA[16][4];
#pragma unroll
    for (int i = 0; i < 16; i++)
#pragma unroll
        for (int r = 0; r < 4; r++) oA[i][r] = 0.f;
    float m0 = -1e30f, m1 = -1e30f, l0 = 0.f, l1 = 0.f;

    const uint32_t kOff = (lane & 15) * 272 + (lane >> 4) * 16;
    const uint32_t vRow = (lane & 15) * 272;
    const uint32_t vCol = (lane >> 4) * 16;

    for (int t = 0; t < NT; t++) {
        const uint32_t kB = sR + ((2 * t) % 3) * FITEM;
        const uint32_t vB = sR + ((2 * t + 1) % 3) * FITEM;

        if (t > 0) { CPWAIT(2); __syncthreads(); }

        float sC[8][4];
#pragma unroll
        for (int i = 0; i < 8; i++)
#pragma unroll
            for (int r = 0; r < 4; r++) sC[i][r] = 0.f;
#pragma unroll
        for (int ks = 0; ks < 8; ks++) {
#pragma unroll
            for (int nbp = 0; nbp < 4; nbp++) {
                uint32_t bf[4];
                ldsm4(bf, kB + nbp * 16 * 272 + kOff + ks * 32);
                mma16816b(sC[2 * nbp],     qf[ks], bf[0], bf[2]);
                mma16816b(sC[2 * nbp + 1], qf[ks], bf[1], bf[3]);
            }
        }

        float mx0 = -1e30f, mx1 = -1e30f;
#pragma unroll
        for (int nb = 0; nb < 8; nb++) {
            mx0 = fmaxf(mx0, fmaxf(sC[nb][0], sC[nb][1]));
            mx1 = fmaxf(mx1, fmaxf(sC[nb][2], sC[nb][3]));
        }
        mx0 = fmaxf(mx0, __shfl_xor_sync(0xffffffffu, mx0, 1));
        mx0 = fmaxf(mx0, __shfl_xor_sync(0xffffffffu, mx0, 2));
        mx1 = fmaxf(mx1, __shfl_xor_sync(0xffffffffu, mx1, 1));
        mx1 = fmaxf(mx1, __shfl_xor_sync(0xffffffffu, mx1, 2));
        float mn0 = fmaxf(m0, mx0), mn1 = fmaxf(m1, mx1);
        float cr0 = exp2f(m0 - mn0), cr1 = exp2f(m1 - mn1);
        m0 = mn0; m1 = mn1;
        float rs0 = 0.f, rs1 = 0.f;
#pragma unroll
        for (int nb = 0; nb < 8; nb++) {
            sC[nb][0] = exp2f(sC[nb][0] - mn0);
            sC[nb][1] = exp2f(sC[nb][1] - mn0);
            sC[nb][2] = exp2f(sC[nb][2] - mn1);
            sC[nb][3] = exp2f(sC[nb][3] - mn1);
            rs0 += sC[nb][0] + sC[nb][1];
            rs1 += sC[nb][2] + sC[nb][3];
        }
        rs0 += __shfl_xor_sync(0xffffffffu, rs0, 1);
        rs0 += __shfl_xor_sync(0xffffffffu, rs0, 2);
        rs1 += __shfl_xor_sync(0xffffffffu, rs1, 1);
        rs1 += __shfl_xor_sync(0xffffffffu, rs1, 2);
        l0 = l0 * cr0 + rs0;
        l1 = l1 * cr1 + rs1;
#pragma unroll
        for (int db = 0; db < 16; db++) {
            oA[db][0] *= cr0; oA[db][1] *= cr0;
            oA[db][2] *= cr1; oA[db][3] *= cr1;
        }

        uint32_t pf[4][4];
#pragma unroll
        for (int s = 0; s < 4; s++) {
            pf[s][0] = packh2(sC[2 * s][0],     sC[2 * s][1]);
            pf[s][1] = packh2(sC[2 * s][2],     sC[2 * s][3]);
            pf[s][2] = packh2(sC[2 * s + 1][0], sC[2 * s + 1][1]);
            pf[s][3] = packh2(sC[2 * s + 1][2], sC[2 * s + 1][3]);
        }

        __syncthreads();
        stageItem(2 * t + 3);
        CPCOMMIT();
        CPWAIT(2);
        __syncthreads();

#pragma unroll
        for (int s = 0; s < 4; s++) {
#pragma unroll
            for (int dbp = 0; dbp < 8; dbp++) {
                uint32_t vf[4];
                ldsm4t(vf, vB + s * 16 * 272 + vRow + (dbp * 16) * 2 + vCol);
                mma16816(oA[2 * dbp],     pf[s], vf);
                mma16816(oA[2 * dbp + 1], pf[s], vf + 2);
            }
        }

        __syncthreads();
        stageItem(2 * t + 4);
        CPCOMMIT();
    }

    const float inv0 = 1.f / l0, inv1 = 1.f / l1;
    const int g = lane >> 2, q = lane & 3;
    const int row = q0 + wid * 16 + g;
    __half* Op = Ah + (size_t)(b * SEQ + row) * DMODEL + h * DKK;
#pragma unroll
    for (int db = 0; db < 16; db++) {
        int col = db * 8 + 2 * q;
        *(__half2*)(Op + col) = __floats2half2_rn(oA[db][0] * inv0, oA[db][1] * inv0);
        *(__half2*)(Op + (size_t)8 * DMODEL + col) =
            __floats2half2_rn(oA[db][2] * inv1, oA[db][3] * inv1);
    }
}

// ---------------------------------------------------------------------------
extern "C" void kernel_launch(void* const* d_in, const int* in_sizes, int n_in,
                              void* d_out, int out_size)
{
    const float* x   = (const float*)d_in[0];
    const float* W_q = (const float*)d_in[1];
    const float* b_q = (const float*)d_in[2];
    const float* W_k = (const float*)d_in[3];
    const float* b_k = (const float*)d_in[4];
    const float* W_v = (const float*)d_in[5];
    const float* b_v = (const float*)d_in[6];
    const float* W_o = (const float*)d_in[7];
    const float* b_o = (const float*)d_in[8];

    float* out = (float*)d_out;
    float* Kc  = out + (size_t)MTOT * DMODEL;
    float* Vc  = Kc  + (size_t)MTOT * DKK;

    __half *xh, *kh, *vh, *ah;
    cudaGetSymbolAddress((void**)&xh, g_xh);
    cudaGetSymbolAddress((void**)&kh, g_kh);
    cudaGetSymbolAddress((void**)&vh, g_vh);
    cudaGetSymbolAddress((void**)&ah, g_ah);

    cudaFuncSetAttribute(gemm_kv, cudaFuncAttributeMaxDynamicSharedMemorySize, GEMM_SMEM);
    cudaFuncSetAttribute(gemm_o,  cudaFuncAttributeMaxDynamicSharedMemorySize, GEMM_SMEM);
    cudaFuncSetAttribute(flash_h, cudaFuncAttributeMaxDynamicSharedMemorySize, FLASH_SMEM);

    // 1/sqrt(128) * log2(e): softmax computed with exp2
    const float qscale = 0.08838834764831845f * 1.4426950408889634f;

    f2h_all<<<(int)(F2H_TOTAL / 4 / 256), 256>>>(x, W_q, W_k, W_v, W_o);

    // K + V projections only (Q fused into flash)
    gemm_kv<<<dim3(2, MTOT / 64), 128, GEMM_SMEM>>>(xh, b_k, b_v, Kc, Vc);

    // flash attention with fused Q projection -> ah (fp16)
    flash_h<<<dim3(SEQ / 64, NHEADS, BATCH), 128, FLASH_SMEM>>>(
        xh, b_q, kh, vh, ah, qscale);

    // output projection -> out (fp32 + bias)
    gemm_o<<<dim3(DMODEL / 128, MTOT / 64), 128, GEMM_SMEM>>>(ah, b_o, out);
}